// round 5
// baseline (speedup 1.0000x reference)
#include <cuda_runtime.h>
#include <cuda_bf16.h>
#include <mma.h>
#include <math.h>
#include <stdint.h>

using namespace nvcuda;

// ---------------- problem constants ----------------
#define BATCH   64
#define SEQ     197
#define TOK     (BATCH*SEQ)      // 12608
#define DIM     768
#define NHEAD   12
#define HDIM    64
#define HID     3072
#define BH      (BATCH*NHEAD)    // 768
#define LN_EPS  1e-6f

// padded attention dims
#define SEQP    208
#define KL      212
#define VL      68

// ---------------- scratch (device globals) ----------------
__device__ float g_q  [(long)BH*SEQ*HDIM];
__device__ float g_k  [(long)BH*SEQ*HDIM];
__device__ float g_v  [(long)BH*SEQ*HDIM];
__device__ float g_ctx[(long)TOK*DIM];
__device__ float g_ao [(long)TOK*DIM];
__device__ float g_x1 [(long)TOK*DIM];
__device__ float g_x1r[(long)TOK*DIM];
__device__ float g_xr [(long)TOK*DIM];
__device__ float g_h  [(long)TOK*HID];
__device__ float g_mlp[(long)TOK*DIM];
__device__ float g_wq [DIM*DIM];
__device__ float g_wk [DIM*DIM];
__device__ float g_wv [DIM*DIM];
__device__ float g_wo [DIM*DIM];
__device__ float g_w1 [DIM*HID];
__device__ float g_w2 [HID*DIM];

__device__ __forceinline__ float tf32r(float x) { return wmma::__float_to_tf32(x); }
__device__ __forceinline__ float gelu_exact(float v) {
    return 0.5f * v * (1.f + erff(v * 0.70710678118654752f));
}
__device__ __forceinline__ void cpa16(uint32_t dst, const float* src) {
    asm volatile("cp.async.cg.shared.global [%0], [%1], 16;" :: "r"(dst), "l"(src) : "memory");
}

// ---------------- tf32 RN rounding kernel (float4) ----------------
__global__ void round_k(const float* __restrict__ src, float* __restrict__ dst, int n4)
{
    int i = blockIdx.x*blockDim.x + threadIdx.x;
    if (i < n4) {
        float4 v = reinterpret_cast<const float4*>(src)[i];
        v.x = tf32r(v.x); v.y = tf32r(v.y); v.z = tf32r(v.z); v.w = tf32r(v.w);
        reinterpret_cast<float4*>(dst)[i] = v;
    }
}

// =====================================================================
// TF32 GEMM, 3-stage cp.async pipeline, single sync per k-step.
// 128x128x32 tiles, 8 warps (64x32 warp tiles), 2 CTAs/SM.
// blockIdx.z selects (B, bias, D, alpha) triple -> fused QKV.
// OUTMODE: 0 plain [M,N]; 1 head-split [(b*12+h)*197+s, dd]
// EPI: 0 none, 1 exact GELU. ROUND: tf32-round output.
// Requires K%32==0, N%128==0. Inputs pre-rounded to tf32.
// =====================================================================
#define STAGE_FLOATS (128*36 + 32*132)          // 8832
#define GEMM_SMEM_BYTES (3*STAGE_FLOATS*4)      // 105984

template<int OUTMODE,int EPI,int ROUND>
__launch_bounds__(256, 2)
__global__ void tgemm_k(const float* __restrict__ A,
                        const float* __restrict__ B0, const float* __restrict__ B1, const float* __restrict__ B2,
                        const float* __restrict__ c0, const float* __restrict__ c1, const float* __restrict__ c2,
                        float* __restrict__ D0, float* __restrict__ D1, float* __restrict__ D2,
                        int M, int N, int K, float a0, float a1, float a2)
{
    extern __shared__ float sm[];
    const uint32_t smBase = (uint32_t)__cvta_generic_to_shared(sm);

    const int z = blockIdx.z;
    const float* Bw   = (z==0) ? B0 : (z==1) ? B1 : B2;
    const float* bias = (z==0) ? c0 : (z==1) ? c1 : c2;
    float*       C    = (z==0) ? D0 : (z==1) ? D1 : D2;
    const float alpha = (z==0) ? a0 : (z==1) ? a1 : a2;

    const int tileM = blockIdx.y * 128;
    const int tileN = blockIdx.x * 128;
    const int tid   = threadIdx.x;
    const int warpId= tid >> 5;
    const int wm    = warpId >> 2;      // 0..1
    const int wn    = warpId & 3;       // 0..3

    const int aRow = tid >> 3;          // 0..31
    const int aCol = (tid & 7) << 2;
    const int bRow = tid >> 5;          // 0..7
    const int bCol = (tid & 31) << 2;

    const float* aPtr[4];
    #pragma unroll
    for (int t=0;t<4;t++) {
        int gm = tileM + t*32 + aRow;
        if (gm > M-1) gm = M-1;
        aPtr[t] = A + (size_t)gm*K + aCol;
    }
    const float* bPtr = Bw + (size_t)bRow*N + tileN + bCol;

    wmma::fragment<wmma::accumulator, 16, 16, 8, float> acc[4][2];
    #pragma unroll
    for (int i=0;i<4;i++)
        #pragma unroll
        for (int j=0;j<2;j++) wmma::fill_fragment(acc[i][j], 0.0f);

    auto issueStage = [&](int k0, int st) {
        const uint32_t ab = smBase + (uint32_t)(st*STAGE_FLOATS)*4;
        const uint32_t bb = ab + (uint32_t)(128*36)*4;
        #pragma unroll
        for (int t=0;t<4;t++)
            cpa16(ab + ((t*32 + aRow)*36 + aCol)*4, aPtr[t] + k0);
        #pragma unroll
        for (int t=0;t<4;t++)
            cpa16(bb + ((t*8 + bRow)*132 + bCol)*4, bPtr + (size_t)(k0 + t*8)*N);
        asm volatile("cp.async.commit_group;" ::: "memory");
    };

    const int NS = K >> 5;
    issueStage(0, 0);
    if (NS > 1) issueStage(32, 1);

    int st = 0;
    for (int s = 0; s < NS; s++) {
        if (s + 1 < NS) asm volatile("cp.async.wait_group 1;" ::: "memory");
        else            asm volatile("cp.async.wait_group 0;" ::: "memory");
        __syncthreads();

        if (s + 2 < NS) {
            int nst = st + 2; if (nst >= 3) nst -= 3;
            issueStage((s+2) << 5, nst);
        }

        const float* Ab = sm + st*STAGE_FLOATS + (wm*64)*36;
        const float* Bb = sm + st*STAGE_FLOATS + 128*36 + wn*32;
        #pragma unroll
        for (int ks=0; ks<4; ks++) {
            wmma::fragment<wmma::matrix_a, 16, 16, 8, wmma::precision::tf32, wmma::row_major> af[4];
            wmma::fragment<wmma::matrix_b, 16, 16, 8, wmma::precision::tf32, wmma::row_major> bf[2];
            #pragma unroll
            for (int i=0;i<4;i++)
                wmma::load_matrix_sync(af[i], Ab + (i*16)*36 + ks*8, 36);
            #pragma unroll
            for (int j=0;j<2;j++)
                wmma::load_matrix_sync(bf[j], Bb + (ks*8)*132 + j*16, 132);
            #pragma unroll
            for (int i=0;i<4;i++)
                #pragma unroll
                for (int j=0;j<2;j++)
                    wmma::mma_sync(acc[i][j], af[i], bf[j], acc[i][j]);
        }
        if (++st == 3) st = 0;
    }
    __syncthreads();

    // ---- epilogue: stage 128x128 tile, coalesced float4 writes ----
    #pragma unroll
    for (int i=0;i<4;i++)
        #pragma unroll
        for (int j=0;j<2;j++)
            wmma::store_matrix_sync(&sm[(wm*64 + i*16)*132 + wn*32 + j*16], acc[i][j], 132,
                                    wmma::mem_row_major);
    __syncthreads();

    const int row  = tid >> 1;
    const int gm   = tileM + row;
    if (gm < M) {
        int b = 0, s = 0;
        if (OUTMODE == 1) { b = gm / SEQ; s = gm - b*SEQ; }
        #pragma unroll
        for (int f=0; f<16; f++) {
            int c  = (tid & 1)*64 + f*4;
            int gn = tileN + c;
            float4 v = *reinterpret_cast<const float4*>(&sm[row*132 + c]);
            v.x = (v.x + bias[gn  ]) * alpha;
            v.y = (v.y + bias[gn+1]) * alpha;
            v.z = (v.z + bias[gn+2]) * alpha;
            v.w = (v.w + bias[gn+3]) * alpha;
            if (EPI == 1) {
                v.x = gelu_exact(v.x); v.y = gelu_exact(v.y);
                v.z = gelu_exact(v.z); v.w = gelu_exact(v.w);
            }
            if (ROUND) {
                v.x = tf32r(v.x); v.y = tf32r(v.y); v.z = tf32r(v.z); v.w = tf32r(v.w);
            }
            if (OUTMODE == 0) {
                *reinterpret_cast<float4*>(&C[(size_t)gm*N + gn]) = v;
            } else {
                int h = gn >> 6, dd = gn & 63;
                size_t orow = (size_t)(b*NHEAD + h)*SEQ + s;
                *reinterpret_cast<float4*>(&C[orow*HDIM + dd]) = v;
            }
        }
    }
}

// =====================================================================
// Fused attention: one CTA per (b,h), 512 threads (16 warps).
// q pre-scaled by 1/8; q,k,v already tf32-rounded.
// =====================================================================
#define ATTN_SMEM_FLOATS (64*KL + SEQP*VL + 64*VL + 64*KL)
#define ATTN_SMEM_BYTES  (ATTN_SMEM_FLOATS*4)

__launch_bounds__(512)
__global__ void attn_k(const float* __restrict__ q, const float* __restrict__ k,
                       const float* __restrict__ v, float* __restrict__ ctx)
{
    extern __shared__ float sm[];
    float* Ksm = sm;
    float* Vsm = Ksm + 64*KL;
    float* QO  = Vsm + SEQP*VL;
    float* Ssm = QO  + 64*VL;

    const int bh = blockIdx.x;
    const int b  = bh / NHEAD;
    const int h  = bh - b*NHEAD;
    const int tid    = threadIdx.x;
    const int warpId = tid >> 5;
    const int lane   = tid & 31;

    const float* qb = q + (size_t)bh*SEQ*HDIM;
    const float* kb = k + (size_t)bh*SEQ*HDIM;
    const float* vb = v + (size_t)bh*SEQ*HDIM;

    for (int idx = tid; idx < SEQP*HDIM; idx += 512) {
        int s = idx >> 6, d = idx & 63;
        Ksm[d*KL + s] = (s < SEQ) ? kb[(size_t)s*HDIM + d] : 0.f;
    }
    for (int idx = tid; idx < SEQP*16; idx += 512) {
        int t = idx >> 4, f = idx & 15;
        float4 val = (t < SEQ) ? *reinterpret_cast<const float4*>(&vb[(size_t)t*HDIM + f*4])
                               : make_float4(0.f,0.f,0.f,0.f);
        *reinterpret_cast<float4*>(&Vsm[t*VL + f*4]) = val;
    }
    __syncthreads();

    for (int s0 = 0; s0 < SEQ; s0 += 64) {
        for (int idx = tid; idx < 64*16; idx += 512) {
            int r = idx >> 4, f = idx & 15;
            int s = s0 + r;
            float4 val = (s < SEQ) ? *reinterpret_cast<const float4*>(&qb[(size_t)s*HDIM + f*4])
                                   : make_float4(0.f,0.f,0.f,0.f);
            *reinterpret_cast<float4*>(&QO[r*VL + f*4]) = val;
        }
        __syncthreads();

        for (int t = warpId; t < 52; t += 16) {
            int mi = t / 13, ni = t - (t/13)*13;
            wmma::fragment<wmma::accumulator, 16, 16, 8, float> sac;
            wmma::fill_fragment(sac, 0.0f);
            #pragma unroll
            for (int ks=0; ks<8; ks++) {
                wmma::fragment<wmma::matrix_a, 16, 16, 8, wmma::precision::tf32, wmma::row_major> af;
                wmma::fragment<wmma::matrix_b, 16, 16, 8, wmma::precision::tf32, wmma::row_major> bf;
                wmma::load_matrix_sync(af, &QO[(mi*16)*VL + ks*8], VL);
                wmma::load_matrix_sync(bf, &Ksm[(ks*8)*KL + ni*16], KL);
                wmma::mma_sync(sac, af, bf, sac);
            }
            wmma::store_matrix_sync(&Ssm[(mi*16)*KL + ni*16], sac, KL, wmma::mem_row_major);
        }
        __syncthreads();

        #pragma unroll
        for (int rr = 0; rr < 4; rr++) {
            int r = warpId*4 + rr;
            float* rowp = &Ssm[r*KL];
            float x[7];
            float m = -1e30f;
            #pragma unroll
            for (int i=0;i<7;i++) {
                int c = lane + i*32;
                x[i] = (c < SEQ) ? rowp[c] : -1e30f;
                m = fmaxf(m, x[i]);
            }
            #pragma unroll
            for (int o=16;o;o>>=1) m = fmaxf(m, __shfl_xor_sync(0xffffffffu, m, o));
            float sum = 0.f;
            #pragma unroll
            for (int i=0;i<7;i++) { x[i] = __expf(x[i] - m); sum += x[i]; }
            #pragma unroll
            for (int o=16;o;o>>=1) sum += __shfl_xor_sync(0xffffffffu, sum, o);
            float inv = 1.f / sum;
            #pragma unroll
            for (int i=0;i<7;i++) {
                int c = lane + i*32;
                if (c < SEQ)       rowp[c] = tf32r(x[i]*inv);
                else if (c < SEQP) rowp[c] = 0.f;
            }
        }
        __syncthreads();

        {
            int mi = warpId >> 2, ni = warpId & 3;
            wmma::fragment<wmma::accumulator, 16, 16, 8, float> oac;
            wmma::fill_fragment(oac, 0.0f);
            #pragma unroll
            for (int ks=0; ks<26; ks++) {
                wmma::fragment<wmma::matrix_a, 16, 16, 8, wmma::precision::tf32, wmma::row_major> af;
                wmma::fragment<wmma::matrix_b, 16, 16, 8, wmma::precision::tf32, wmma::row_major> bf;
                wmma::load_matrix_sync(af, &Ssm[(mi*16)*KL + ks*8], KL);
                wmma::load_matrix_sync(bf, &Vsm[(ks*8)*VL + ni*16], VL);
                wmma::mma_sync(oac, af, bf, oac);
            }
            wmma::store_matrix_sync(&QO[(mi*16)*VL + ni*16], oac, VL, wmma::mem_row_major);
        }
        __syncthreads();

        for (int idx = tid; idx < 64*16; idx += 512) {
            int r = idx >> 4, f = idx & 15;
            int s = s0 + r;
            if (s < SEQ) {
                float4 val = *reinterpret_cast<const float4*>(&QO[r*VL + f*4]);
                val.x=tf32r(val.x); val.y=tf32r(val.y); val.z=tf32r(val.z); val.w=tf32r(val.w);
                *reinterpret_cast<float4*>(&ctx[((size_t)(b*SEQ + s))*DIM + h*HDIM + f*4]) = val;
            }
        }
        __syncthreads();
    }
}

// ---------------- residual + LayerNorm (optional rounded copy) ----------------
__global__ void add_ln_k(const float* __restrict__ x, const float* __restrict__ y,
                         const float* __restrict__ g, const float* __restrict__ be,
                         float* __restrict__ out, float* __restrict__ outR)
{
    const int r = blockIdx.x;
    const float* yr = y + (long)r*DIM;
    const float* xr = x + (long)r*DIM;

    float s = 0.f, sq = 0.f;
    for (int i = threadIdx.x; i < DIM; i += blockDim.x) {
        float t = yr[i]; s += t; sq += t*t;
    }
    __shared__ float red[64];
    #pragma unroll
    for (int o=16;o;o>>=1) { s += __shfl_xor_sync(0xffffffffu, s, o); sq += __shfl_xor_sync(0xffffffffu, sq, o); }
    int w = threadIdx.x >> 5, lane = threadIdx.x & 31;
    if (lane == 0) { red[w] = s; red[w+32] = sq; }
    __syncthreads();
    if (threadIdx.x < 32) {
        int nw = blockDim.x >> 5;
        s  = (threadIdx.x < nw) ? red[threadIdx.x]      : 0.f;
        sq = (threadIdx.x < nw) ? red[threadIdx.x + 32] : 0.f;
        #pragma unroll
        for (int o=16;o;o>>=1) { s += __shfl_xor_sync(0xffffffffu, s, o); sq += __shfl_xor_sync(0xffffffffu, sq, o); }
        if (threadIdx.x == 0) { red[0] = s; red[1] = sq; }
    }
    __syncthreads();
    float mu   = red[0] * (1.f/DIM);
    float var  = red[1] * (1.f/DIM) - mu*mu;
    float rstd = rsqrtf(var + LN_EPS);
    for (int i = threadIdx.x; i < DIM; i += blockDim.x) {
        float val = xr[i] + (yr[i] - mu) * rstd * g[i] + be[i];
        out[(long)r*DIM + i] = val;
        if (outR) outR[(long)r*DIM + i] = tf32r(val);
    }
}

// ---------------- launch ----------------
extern "C" void kernel_launch(void* const* d_in, const int* in_sizes, int n_in,
                              void* d_out, int out_size)
{
    const float* x   = (const float*)d_in[0];
    const float* Wq  = (const float*)d_in[1];
    const float* bq  = (const float*)d_in[2];
    const float* Wk  = (const float*)d_in[3];
    const float* bk  = (const float*)d_in[4];
    const float* Wv  = (const float*)d_in[5];
    const float* bv  = (const float*)d_in[6];
    const float* Wo  = (const float*)d_in[7];
    const float* bo  = (const float*)d_in[8];
    const float* W1  = (const float*)d_in[9];
    const float* b1  = (const float*)d_in[10];
    const float* W2  = (const float*)d_in[11];
    const float* b2  = (const float*)d_in[12];
    const float* g1  = (const float*)d_in[13];
    const float* be1 = (const float*)d_in[14];
    const float* g2  = (const float*)d_in[15];
    const float* be2 = (const float*)d_in[16];
    float* out = (float*)d_out;

    float *q,*k,*v,*ctx,*ao,*x1,*x1r,*xr,*hh,*mlp,*wq,*wk,*wv,*wo,*w1,*w2;
    cudaGetSymbolAddress((void**)&q,   g_q);
    cudaGetSymbolAddress((void**)&k,   g_k);
    cudaGetSymbolAddress((void**)&v,   g_v);
    cudaGetSymbolAddress((void**)&ctx, g_ctx);
    cudaGetSymbolAddress((void**)&ao,  g_ao);
    cudaGetSymbolAddress((void**)&x1,  g_x1);
    cudaGetSymbolAddress((void**)&x1r, g_x1r);
    cudaGetSymbolAddress((void**)&xr,  g_xr);
    cudaGetSymbolAddress((void**)&hh,  g_h);
    cudaGetSymbolAddress((void**)&mlp, g_mlp);
    cudaGetSymbolAddress((void**)&wq,  g_wq);
    cudaGetSymbolAddress((void**)&wk,  g_wk);
    cudaGetSymbolAddress((void**)&wv,  g_wv);
    cudaGetSymbolAddress((void**)&wo,  g_wo);
    cudaGetSymbolAddress((void**)&w1,  g_w1);
    cudaGetSymbolAddress((void**)&w2,  g_w2);

    cudaFuncSetAttribute(tgemm_k<1,0,1>, cudaFuncAttributeMaxDynamicSharedMemorySize, GEMM_SMEM_BYTES);
    cudaFuncSetAttribute(tgemm_k<0,0,0>, cudaFuncAttributeMaxDynamicSharedMemorySize, GEMM_SMEM_BYTES);
    cudaFuncSetAttribute(tgemm_k<0,1,1>, cudaFuncAttributeMaxDynamicSharedMemorySize, GEMM_SMEM_BYTES);
    cudaFuncSetAttribute(attn_k,         cudaFuncAttributeMaxDynamicSharedMemorySize, ATTN_SMEM_BYTES);

    // --- tf32-round weights + x ---
    {
        const int T = 256;
        int n;
        n = DIM*DIM/4;   round_k<<<(n+T-1)/T, T>>>(Wq, wq, n);
        n = DIM*DIM/4;   round_k<<<(n+T-1)/T, T>>>(Wk, wk, n);
        n = DIM*DIM/4;   round_k<<<(n+T-1)/T, T>>>(Wv, wv, n);
        n = DIM*DIM/4;   round_k<<<(n+T-1)/T, T>>>(Wo, wo, n);
        n = DIM*HID/4;   round_k<<<(n+T-1)/T, T>>>(W1, w1, n);
        n = HID*DIM/4;   round_k<<<(n+T-1)/T, T>>>(W2, w2, n);
        n = TOK*DIM/4;   round_k<<<(n+T-1)/T, T>>>(x,  xr, n);
    }

    const int mtiles = (TOK + 127)/128;   // 99

    // --- fused QKV projection (one launch, z picks W/bias/out/alpha) ---
    {
        dim3 grid(DIM/128, mtiles, 3);
        tgemm_k<1,0,1><<<grid, 256, GEMM_SMEM_BYTES>>>(xr, wq, wk, wv, bq, bk, bv,
                                                       q, k, v, TOK, DIM, DIM,
                                                       0.125f, 1.0f, 1.0f);
    }

    // --- fused attention -> ctx (rounded) ---
    attn_k<<<BH, 512, ATTN_SMEM_BYTES>>>(q, k, v, ctx);

    // --- attn_out = ctx @ Wo + bo ---
    {
        dim3 grid(DIM/128, mtiles, 1);
        tgemm_k<0,0,0><<<grid, 256, GEMM_SMEM_BYTES>>>(ctx, wo, wo, wo, bo, bo, bo,
                                                       ao, ao, ao, TOK, DIM, DIM,
                                                       1.0f, 1.0f, 1.0f);
    }

    // --- x1 = x + LN(attn_out); rounded copy for MLP1 ---
    add_ln_k<<<TOK, 256>>>(x, ao, g1, be1, x1, x1r);

    // --- h = gelu(x1 @ W1 + b1) (rounded) ---
    {
        dim3 grid(HID/128, mtiles, 1);
        tgemm_k<0,1,1><<<grid, 256, GEMM_SMEM_BYTES>>>(x1r, w1, w1, w1, b1, b1, b1,
                                                       hh, hh, hh, TOK, HID, DIM,
                                                       1.0f, 1.0f, 1.0f);
    }

    // --- mlp = h @ W2 + b2 ---
    {
        dim3 grid(DIM/128, mtiles, 1);
        tgemm_k<0,0,0><<<grid, 256, GEMM_SMEM_BYTES>>>(hh, w2, w2, w2, b2, b2, b2,
                                                       mlp, mlp, mlp, TOK, DIM, HID,
                                                       1.0f, 1.0f, 1.0f);
    }

    // --- out = x1 + LN(mlp) ---
    add_ln_k<<<TOK, 256>>>(x1, mlp, g2, be2, out, nullptr);
}

// round 6
// speedup vs baseline: 1.0439x; 1.0439x over previous
#include <cuda_runtime.h>
#include <cuda_bf16.h>
#include <mma.h>
#include <math.h>
#include <stdint.h>

using namespace nvcuda;

// ---------------- problem constants ----------------
#define BATCH   64
#define SEQ     197
#define TOK     (BATCH*SEQ)      // 12608
#define DIM     768
#define NHEAD   12
#define HDIM    64
#define HID     3072
#define BH      (BATCH*NHEAD)    // 768
#define LN_EPS  1e-6f

// padded attention dims
#define SEQP    208
#define KL      212
#define VL      68

// ---------------- scratch (device globals) ----------------
__device__ float g_q  [(long)BH*SEQ*HDIM];
__device__ float g_k  [(long)BH*SEQ*HDIM];
__device__ float g_v  [(long)BH*SEQ*HDIM];
__device__ float g_ctx[(long)TOK*DIM];
__device__ float g_ao [(long)TOK*DIM];
__device__ float g_x1 [(long)TOK*DIM];
__device__ float g_x1r[(long)TOK*DIM];
__device__ float g_xr [(long)TOK*DIM];
__device__ float g_h  [(long)TOK*HID];
__device__ float g_mlp[(long)TOK*DIM];
__device__ float g_wq [DIM*DIM];
__device__ float g_wk [DIM*DIM];
__device__ float g_wv [DIM*DIM];
__device__ float g_wo [DIM*DIM];
__device__ float g_w1 [DIM*HID];
__device__ float g_w2 [HID*DIM];

__device__ __forceinline__ float tf32r(float x) { return wmma::__float_to_tf32(x); }
__device__ __forceinline__ float gelu_exact(float v) {
    return 0.5f * v * (1.f + erff(v * 0.70710678118654752f));
}
__device__ __forceinline__ void cpa16(uint32_t dst, const float* src) {
    asm volatile("cp.async.cg.shared.global [%0], [%1], 16;" :: "r"(dst), "l"(src) : "memory");
}

// ---------------- tf32 RN rounding kernel (float4) ----------------
__global__ void round_k(const float* __restrict__ src, float* __restrict__ dst, int n4)
{
    int i = blockIdx.x*blockDim.x + threadIdx.x;
    if (i < n4) {
        float4 v = reinterpret_cast<const float4*>(src)[i];
        v.x = tf32r(v.x); v.y = tf32r(v.y); v.z = tf32r(v.z); v.w = tf32r(v.w);
        reinterpret_cast<float4*>(dst)[i] = v;
    }
}

// =====================================================================
// TF32 GEMM: 256x128x32 tiles, 8 warps (64x64 warp tiles),
// 3-stage cp.async pipeline, SINGLE __syncthreads per k-step.
// blockIdx.z selects (B, bias, D, alpha) -> fused QKV.
// OUTMODE: 0 plain [M,N]; 1 head-split [(b*12+h)*197+s, dd]
// EPI: 0 none, 1 exact GELU. ROUND: tf32-round output.
// Requires K%32==0, N%128==0. Inputs pre-rounded to tf32.
// =====================================================================
#define STAGE_FLOATS (256*36 + 32*132)            // 13440
#define GEMM_SMEM_BYTES (3*STAGE_FLOATS*4)        // 161280; epilogue 256*132*4=135168 fits

template<int OUTMODE,int EPI,int ROUND>
__launch_bounds__(256)
__global__ void tgemm_k(const float* __restrict__ A,
                        const float* __restrict__ B0, const float* __restrict__ B1, const float* __restrict__ B2,
                        const float* __restrict__ c0, const float* __restrict__ c1, const float* __restrict__ c2,
                        float* __restrict__ D0, float* __restrict__ D1, float* __restrict__ D2,
                        int M, int N, int K, float a0, float a1, float a2)
{
    extern __shared__ float sm[];
    const uint32_t smBase = (uint32_t)__cvta_generic_to_shared(sm);

    const int z = blockIdx.z;
    const float* Bw   = (z==0) ? B0 : (z==1) ? B1 : B2;
    const float* bias = (z==0) ? c0 : (z==1) ? c1 : c2;
    float*       C    = (z==0) ? D0 : (z==1) ? D1 : D2;
    const float alpha = (z==0) ? a0 : (z==1) ? a1 : a2;

    const int tileM = blockIdx.y * 256;
    const int tileN = blockIdx.x * 128;
    const int tid   = threadIdx.x;
    const int warpId= tid >> 5;
    const int wm    = warpId >> 1;      // 0..3
    const int wn    = warpId & 1;       // 0..1

    const int aRow = tid >> 3;          // 0..31
    const int aCol = (tid & 7) << 2;    // 0..28
    const int bRow = tid >> 5;          // 0..7
    const int bCol = (tid & 31) << 2;   // 0..124

    const float* aPtr[8];
    #pragma unroll
    for (int t=0;t<8;t++) {
        int gm = tileM + t*32 + aRow;
        if (gm > M-1) gm = M-1;
        aPtr[t] = A + (size_t)gm*K + aCol;
    }
    const float* bPtr = Bw + (size_t)bRow*N + tileN + bCol;

    wmma::fragment<wmma::accumulator, 16, 16, 8, float> acc[4][4];
    #pragma unroll
    for (int i=0;i<4;i++)
        #pragma unroll
        for (int j=0;j<4;j++) wmma::fill_fragment(acc[i][j], 0.0f);

    auto issueStage = [&](int k0, int st) {
        const uint32_t ab = smBase + (uint32_t)(st*STAGE_FLOATS)*4;
        const uint32_t bb = ab + (uint32_t)(256*36)*4;
        #pragma unroll
        for (int t=0;t<8;t++)
            cpa16(ab + ((t*32 + aRow)*36 + aCol)*4, aPtr[t] + k0);
        #pragma unroll
        for (int t=0;t<4;t++)
            cpa16(bb + ((t*8 + bRow)*132 + bCol)*4, bPtr + (size_t)(k0 + t*8)*N);
        asm volatile("cp.async.commit_group;" ::: "memory");
    };

    const int NS = K >> 5;
    issueStage(0, 0);
    if (NS > 1) issueStage(32, 1);

    int st = 0;
    for (int s = 0; s < NS; s++) {
        if (s + 1 < NS) asm volatile("cp.async.wait_group 1;" ::: "memory");
        else            asm volatile("cp.async.wait_group 0;" ::: "memory");
        __syncthreads();

        if (s + 2 < NS) {
            int nst = st + 2; if (nst >= 3) nst -= 3;
            issueStage((s+2) << 5, nst);
        }

        const float* Ab = sm + st*STAGE_FLOATS + (wm*64)*36;
        const float* Bb = sm + st*STAGE_FLOATS + 256*36 + wn*64;
        #pragma unroll
        for (int ks=0; ks<4; ks++) {
            wmma::fragment<wmma::matrix_a, 16, 16, 8, wmma::precision::tf32, wmma::row_major> af[4];
            wmma::fragment<wmma::matrix_b, 16, 16, 8, wmma::precision::tf32, wmma::row_major> bf[4];
            #pragma unroll
            for (int i=0;i<4;i++)
                wmma::load_matrix_sync(af[i], Ab + (i*16)*36 + ks*8, 36);
            #pragma unroll
            for (int j=0;j<4;j++)
                wmma::load_matrix_sync(bf[j], Bb + (ks*8)*132 + j*16, 132);
            #pragma unroll
            for (int i=0;i<4;i++)
                #pragma unroll
                for (int j=0;j<4;j++)
                    wmma::mma_sync(acc[i][j], af[i], bf[j], acc[i][j]);
        }
        if (++st == 3) st = 0;
    }
    __syncthreads();

    // ---- epilogue: stage 256x128 tile, coalesced float4 writes ----
    #pragma unroll
    for (int i=0;i<4;i++)
        #pragma unroll
        for (int j=0;j<4;j++)
            wmma::store_matrix_sync(&sm[(wm*64 + i*16)*132 + wn*64 + j*16], acc[i][j], 132,
                                    wmma::mem_row_major);
    __syncthreads();

    #pragma unroll
    for (int rr=0; rr<2; rr++) {
        const int row = rr*128 + (tid >> 1);
        const int gm  = tileM + row;
        if (gm >= M) continue;
        int b = 0, s = 0;
        if (OUTMODE == 1) { b = gm / SEQ; s = gm - b*SEQ; }
        #pragma unroll
        for (int f=0; f<16; f++) {
            int c  = (tid & 1)*64 + f*4;
            int gn = tileN + c;
            float4 v = *reinterpret_cast<const float4*>(&sm[row*132 + c]);
            v.x = (v.x + bias[gn  ]) * alpha;
            v.y = (v.y + bias[gn+1]) * alpha;
            v.z = (v.z + bias[gn+2]) * alpha;
            v.w = (v.w + bias[gn+3]) * alpha;
            if (EPI == 1) {
                v.x = gelu_exact(v.x); v.y = gelu_exact(v.y);
                v.z = gelu_exact(v.z); v.w = gelu_exact(v.w);
            }
            if (ROUND) {
                v.x = tf32r(v.x); v.y = tf32r(v.y); v.z = tf32r(v.z); v.w = tf32r(v.w);
            }
            if (OUTMODE == 0) {
                *reinterpret_cast<float4*>(&C[(size_t)gm*N + gn]) = v;
            } else {
                int h = gn >> 6, dd = gn & 63;
                size_t orow = (size_t)(b*NHEAD + h)*SEQ + s;
                *reinterpret_cast<float4*>(&C[orow*HDIM + dd]) = v;
            }
        }
    }
}

// =====================================================================
// Fused attention: one CTA per (b,h), 512 threads (16 warps).
// q pre-scaled by 1/8; q,k,v already tf32-rounded.
// =====================================================================
#define ATTN_SMEM_FLOATS (64*KL + SEQP*VL + 64*VL + 64*KL)
#define ATTN_SMEM_BYTES  (ATTN_SMEM_FLOATS*4)

__launch_bounds__(512)
__global__ void attn_k(const float* __restrict__ q, const float* __restrict__ k,
                       const float* __restrict__ v, float* __restrict__ ctx)
{
    extern __shared__ float sm[];
    float* Ksm = sm;
    float* Vsm = Ksm + 64*KL;
    float* QO  = Vsm + SEQP*VL;
    float* Ssm = QO  + 64*VL;

    const int bh = blockIdx.x;
    const int b  = bh / NHEAD;
    const int h  = bh - b*NHEAD;
    const int tid    = threadIdx.x;
    const int warpId = tid >> 5;
    const int lane   = tid & 31;

    const float* qb = q + (size_t)bh*SEQ*HDIM;
    const float* kb = k + (size_t)bh*SEQ*HDIM;
    const float* vb = v + (size_t)bh*SEQ*HDIM;

    for (int idx = tid; idx < SEQP*HDIM; idx += 512) {
        int s = idx >> 6, d = idx & 63;
        Ksm[d*KL + s] = (s < SEQ) ? kb[(size_t)s*HDIM + d] : 0.f;
    }
    for (int idx = tid; idx < SEQP*16; idx += 512) {
        int t = idx >> 4, f = idx & 15;
        float4 val = (t < SEQ) ? *reinterpret_cast<const float4*>(&vb[(size_t)t*HDIM + f*4])
                               : make_float4(0.f,0.f,0.f,0.f);
        *reinterpret_cast<float4*>(&Vsm[t*VL + f*4]) = val;
    }
    __syncthreads();

    for (int s0 = 0; s0 < SEQ; s0 += 64) {
        for (int idx = tid; idx < 64*16; idx += 512) {
            int r = idx >> 4, f = idx & 15;
            int s = s0 + r;
            float4 val = (s < SEQ) ? *reinterpret_cast<const float4*>(&qb[(size_t)s*HDIM + f*4])
                                   : make_float4(0.f,0.f,0.f,0.f);
            *reinterpret_cast<float4*>(&QO[r*VL + f*4]) = val;
        }
        __syncthreads();

        for (int t = warpId; t < 52; t += 16) {
            int mi = t / 13, ni = t - (t/13)*13;
            wmma::fragment<wmma::accumulator, 16, 16, 8, float> sac;
            wmma::fill_fragment(sac, 0.0f);
            #pragma unroll
            for (int ks=0; ks<8; ks++) {
                wmma::fragment<wmma::matrix_a, 16, 16, 8, wmma::precision::tf32, wmma::row_major> af;
                wmma::fragment<wmma::matrix_b, 16, 16, 8, wmma::precision::tf32, wmma::row_major> bf;
                wmma::load_matrix_sync(af, &QO[(mi*16)*VL + ks*8], VL);
                wmma::load_matrix_sync(bf, &Ksm[(ks*8)*KL + ni*16], KL);
                wmma::mma_sync(sac, af, bf, sac);
            }
            wmma::store_matrix_sync(&Ssm[(mi*16)*KL + ni*16], sac, KL, wmma::mem_row_major);
        }
        __syncthreads();

        #pragma unroll
        for (int rr = 0; rr < 4; rr++) {
            int r = warpId*4 + rr;
            float* rowp = &Ssm[r*KL];
            float x[7];
            float m = -1e30f;
            #pragma unroll
            for (int i=0;i<7;i++) {
                int c = lane + i*32;
                x[i] = (c < SEQ) ? rowp[c] : -1e30f;
                m = fmaxf(m, x[i]);
            }
            #pragma unroll
            for (int o=16;o;o>>=1) m = fmaxf(m, __shfl_xor_sync(0xffffffffu, m, o));
            float sum = 0.f;
            #pragma unroll
            for (int i=0;i<7;i++) { x[i] = __expf(x[i] - m); sum += x[i]; }
            #pragma unroll
            for (int o=16;o;o>>=1) sum += __shfl_xor_sync(0xffffffffu, sum, o);
            float inv = 1.f / sum;
            #pragma unroll
            for (int i=0;i<7;i++) {
                int c = lane + i*32;
                if (c < SEQ)       rowp[c] = tf32r(x[i]*inv);
                else if (c < SEQP) rowp[c] = 0.f;
            }
        }
        __syncthreads();

        {
            int mi = warpId >> 2, ni = warpId & 3;
            wmma::fragment<wmma::accumulator, 16, 16, 8, float> oac;
            wmma::fill_fragment(oac, 0.0f);
            #pragma unroll
            for (int ks=0; ks<26; ks++) {
                wmma::fragment<wmma::matrix_a, 16, 16, 8, wmma::precision::tf32, wmma::row_major> af;
                wmma::fragment<wmma::matrix_b, 16, 16, 8, wmma::precision::tf32, wmma::row_major> bf;
                wmma::load_matrix_sync(af, &Ssm[(mi*16)*KL + ks*8], KL);
                wmma::load_matrix_sync(bf, &Vsm[(ks*8)*VL + ni*16], VL);
                wmma::mma_sync(oac, af, bf, oac);
            }
            wmma::store_matrix_sync(&QO[(mi*16)*VL + ni*16], oac, VL, wmma::mem_row_major);
        }
        __syncthreads();

        for (int idx = tid; idx < 64*16; idx += 512) {
            int r = idx >> 4, f = idx & 15;
            int s = s0 + r;
            if (s < SEQ) {
                float4 val = *reinterpret_cast<const float4*>(&QO[r*VL + f*4]);
                val.x=tf32r(val.x); val.y=tf32r(val.y); val.z=tf32r(val.z); val.w=tf32r(val.w);
                *reinterpret_cast<float4*>(&ctx[((size_t)(b*SEQ + s))*DIM + h*HDIM + f*4]) = val;
            }
        }
        __syncthreads();
    }
}

// ---------------- residual + LayerNorm (optional rounded copy) ----------------
__global__ void add_ln_k(const float* __restrict__ x, const float* __restrict__ y,
                         const float* __restrict__ g, const float* __restrict__ be,
                         float* __restrict__ out, float* __restrict__ outR)
{
    const int r = blockIdx.x;
    const float* yr = y + (long)r*DIM;
    const float* xr = x + (long)r*DIM;

    float s = 0.f, sq = 0.f;
    for (int i = threadIdx.x; i < DIM; i += blockDim.x) {
        float t = yr[i]; s += t; sq += t*t;
    }
    __shared__ float red[64];
    #pragma unroll
    for (int o=16;o;o>>=1) { s += __shfl_xor_sync(0xffffffffu, s, o); sq += __shfl_xor_sync(0xffffffffu, sq, o); }
    int w = threadIdx.x >> 5, lane = threadIdx.x & 31;
    if (lane == 0) { red[w] = s; red[w+32] = sq; }
    __syncthreads();
    if (threadIdx.x < 32) {
        int nw = blockDim.x >> 5;
        s  = (threadIdx.x < nw) ? red[threadIdx.x]      : 0.f;
        sq = (threadIdx.x < nw) ? red[threadIdx.x + 32] : 0.f;
        #pragma unroll
        for (int o=16;o;o>>=1) { s += __shfl_xor_sync(0xffffffffu, s, o); sq += __shfl_xor_sync(0xffffffffu, sq, o); }
        if (threadIdx.x == 0) { red[0] = s; red[1] = sq; }
    }
    __syncthreads();
    float mu   = red[0] * (1.f/DIM);
    float var  = red[1] * (1.f/DIM) - mu*mu;
    float rstd = rsqrtf(var + LN_EPS);
    for (int i = threadIdx.x; i < DIM; i += blockDim.x) {
        float val = xr[i] + (yr[i] - mu) * rstd * g[i] + be[i];
        out[(long)r*DIM + i] = val;
        if (outR) outR[(long)r*DIM + i] = tf32r(val);
    }
}

// ---------------- launch ----------------
extern "C" void kernel_launch(void* const* d_in, const int* in_sizes, int n_in,
                              void* d_out, int out_size)
{
    const float* x   = (const float*)d_in[0];
    const float* Wq  = (const float*)d_in[1];
    const float* bq  = (const float*)d_in[2];
    const float* Wk  = (const float*)d_in[3];
    const float* bk  = (const float*)d_in[4];
    const float* Wv  = (const float*)d_in[5];
    const float* bv  = (const float*)d_in[6];
    const float* Wo  = (const float*)d_in[7];
    const float* bo  = (const float*)d_in[8];
    const float* W1  = (const float*)d_in[9];
    const float* b1  = (const float*)d_in[10];
    const float* W2  = (const float*)d_in[11];
    const float* b2  = (const float*)d_in[12];
    const float* g1  = (const float*)d_in[13];
    const float* be1 = (const float*)d_in[14];
    const float* g2  = (const float*)d_in[15];
    const float* be2 = (const float*)d_in[16];
    float* out = (float*)d_out;

    float *q,*k,*v,*ctx,*ao,*x1,*x1r,*xr,*hh,*mlp,*wq,*wk,*wv,*wo,*w1,*w2;
    cudaGetSymbolAddress((void**)&q,   g_q);
    cudaGetSymbolAddress((void**)&k,   g_k);
    cudaGetSymbolAddress((void**)&v,   g_v);
    cudaGetSymbolAddress((void**)&ctx, g_ctx);
    cudaGetSymbolAddress((void**)&ao,  g_ao);
    cudaGetSymbolAddress((void**)&x1,  g_x1);
    cudaGetSymbolAddress((void**)&x1r, g_x1r);
    cudaGetSymbolAddress((void**)&xr,  g_xr);
    cudaGetSymbolAddress((void**)&hh,  g_h);
    cudaGetSymbolAddress((void**)&mlp, g_mlp);
    cudaGetSymbolAddress((void**)&wq,  g_wq);
    cudaGetSymbolAddress((void**)&wk,  g_wk);
    cudaGetSymbolAddress((void**)&wv,  g_wv);
    cudaGetSymbolAddress((void**)&wo,  g_wo);
    cudaGetSymbolAddress((void**)&w1,  g_w1);
    cudaGetSymbolAddress((void**)&w2,  g_w2);

    cudaFuncSetAttribute(tgemm_k<1,0,1>, cudaFuncAttributeMaxDynamicSharedMemorySize, GEMM_SMEM_BYTES);
    cudaFuncSetAttribute(tgemm_k<0,0,0>, cudaFuncAttributeMaxDynamicSharedMemorySize, GEMM_SMEM_BYTES);
    cudaFuncSetAttribute(tgemm_k<0,1,1>, cudaFuncAttributeMaxDynamicSharedMemorySize, GEMM_SMEM_BYTES);
    cudaFuncSetAttribute(attn_k,         cudaFuncAttributeMaxDynamicSharedMemorySize, ATTN_SMEM_BYTES);

    // --- tf32-round weights + x ---
    {
        const int T = 256;
        int n;
        n = DIM*DIM/4;   round_k<<<(n+T-1)/T, T>>>(Wq, wq, n);
        n = DIM*DIM/4;   round_k<<<(n+T-1)/T, T>>>(Wk, wk, n);
        n = DIM*DIM/4;   round_k<<<(n+T-1)/T, T>>>(Wv, wv, n);
        n = DIM*DIM/4;   round_k<<<(n+T-1)/T, T>>>(Wo, wo, n);
        n = DIM*HID/4;   round_k<<<(n+T-1)/T, T>>>(W1, w1, n);
        n = HID*DIM/4;   round_k<<<(n+T-1)/T, T>>>(W2, w2, n);
        n = TOK*DIM/4;   round_k<<<(n+T-1)/T, T>>>(x,  xr, n);
    }

    const int mtiles = (TOK + 255)/256;   // 50

    // --- fused QKV projection (one launch, z picks W/bias/out/alpha) ---
    {
        dim3 grid(DIM/128, mtiles, 3);
        tgemm_k<1,0,1><<<grid, 256, GEMM_SMEM_BYTES>>>(xr, wq, wk, wv, bq, bk, bv,
                                                       q, k, v, TOK, DIM, DIM,
                                                       0.125f, 1.0f, 1.0f);
    }

    // --- fused attention -> ctx (rounded) ---
    attn_k<<<BH, 512, ATTN_SMEM_BYTES>>>(q, k, v, ctx);

    // --- attn_out = ctx @ Wo + bo ---
    {
        dim3 grid(DIM/128, mtiles, 1);
        tgemm_k<0,0,0><<<grid, 256, GEMM_SMEM_BYTES>>>(ctx, wo, wo, wo, bo, bo, bo,
                                                       ao, ao, ao, TOK, DIM, DIM,
                                                       1.0f, 1.0f, 1.0f);
    }

    // --- x1 = x + LN(attn_out); rounded copy for MLP1 ---
    add_ln_k<<<TOK, 256>>>(x, ao, g1, be1, x1, x1r);

    // --- h = gelu(x1 @ W1 + b1) (rounded) ---
    {
        dim3 grid(HID/128, mtiles, 1);
        tgemm_k<0,1,1><<<grid, 256, GEMM_SMEM_BYTES>>>(x1r, w1, w1, w1, b1, b1, b1,
                                                       hh, hh, hh, TOK, HID, DIM,
                                                       1.0f, 1.0f, 1.0f);
    }

    // --- mlp = h @ W2 + b2 ---
    {
        dim3 grid(DIM/128, mtiles, 1);
        tgemm_k<0,0,0><<<grid, 256, GEMM_SMEM_BYTES>>>(hh, w2, w2, w2, b2, b2, b2,
                                                       mlp, mlp, mlp, TOK, DIM, HID,
                                                       1.0f, 1.0f, 1.0f);
    }

    // --- out = x1 + LN(mlp) ---
    add_ln_k<<<TOK, 256>>>(x1, mlp, g2, be2, out, nullptr);
}

// round 7
// speedup vs baseline: 1.7336x; 1.6607x over previous
#include <cuda_runtime.h>
#include <cuda_bf16.h>
#include <mma.h>
#include <math.h>
#include <stdint.h>

using namespace nvcuda;

// ---------------- problem constants ----------------
#define BATCH   64
#define SEQ     197
#define TOK     (BATCH*SEQ)      // 12608
#define DIM     768
#define NHEAD   12
#define HDIM    64
#define HID     3072
#define BH      (BATCH*NHEAD)    // 768
#define LN_EPS  1e-6f

// padded attention dims
#define SEQP    208
#define KL      212
#define VL      68

// ---------------- scratch (device globals) ----------------
__device__ float g_q  [(long)BH*SEQ*HDIM];
__device__ float g_k  [(long)BH*SEQ*HDIM];
__device__ float g_v  [(long)BH*SEQ*HDIM];
__device__ float g_ctx[(long)TOK*DIM];
__device__ float g_ao [(long)TOK*DIM];
__device__ float g_x1 [(long)TOK*DIM];
__device__ float g_x1r[(long)TOK*DIM];
__device__ float g_xr [(long)TOK*DIM];
__device__ float g_h  [(long)TOK*HID];
__device__ float g_mlp[(long)TOK*DIM];
// transposed + tf32-rounded weights: [N][K]
__device__ float g_wqT[DIM*DIM];
__device__ float g_wkT[DIM*DIM];
__device__ float g_wvT[DIM*DIM];
__device__ float g_woT[DIM*DIM];
__device__ float g_w1T[(long)HID*DIM];
__device__ float g_w2T[(long)DIM*HID];

__device__ __forceinline__ float tf32r(float x) { return wmma::__float_to_tf32(x); }
__device__ __forceinline__ float gelu_exact(float v) {
    return 0.5f * v * (1.f + erff(v * 0.70710678118654752f));
}
__device__ __forceinline__ void cpa16(uint32_t dst, const float* src) {
    asm volatile("cp.async.cg.shared.global [%0], [%1], 16;" :: "r"(dst), "l"(src) : "memory");
}
__device__ __forceinline__ void ldsm4(uint32_t addr, uint32_t& r0, uint32_t& r1,
                                      uint32_t& r2, uint32_t& r3) {
    asm volatile("ldmatrix.sync.aligned.m8n8.x4.shared.b16 {%0,%1,%2,%3}, [%4];"
                 : "=r"(r0), "=r"(r1), "=r"(r2), "=r"(r3) : "r"(addr));
}
__device__ __forceinline__ void mma_tf32(float* c, uint32_t a0, uint32_t a1,
                                         uint32_t a2, uint32_t a3,
                                         uint32_t b0, uint32_t b1) {
    asm volatile("mma.sync.aligned.m16n8k8.row.col.f32.tf32.tf32.f32 "
                 "{%0,%1,%2,%3}, {%4,%5,%6,%7}, {%8,%9}, {%0,%1,%2,%3};"
                 : "+f"(c[0]), "+f"(c[1]), "+f"(c[2]), "+f"(c[3])
                 : "r"(a0), "r"(a1), "r"(a2), "r"(a3), "r"(b0), "r"(b1));
}

// ---------------- tf32 RN rounding kernel (float4) ----------------
__global__ void round_k(const float* __restrict__ src, float* __restrict__ dst, int n4)
{
    int i = blockIdx.x*blockDim.x + threadIdx.x;
    if (i < n4) {
        float4 v = reinterpret_cast<const float4*>(src)[i];
        v.x = tf32r(v.x); v.y = tf32r(v.y); v.z = tf32r(v.z); v.w = tf32r(v.w);
        reinterpret_cast<float4*>(dst)[i] = v;
    }
}

// ---------------- transpose + tf32-round: src[K][N] -> dst[N][K] ----------------
__global__ void troundT_k(const float* __restrict__ src, float* __restrict__ dst,
                          int K, int N)
{
    __shared__ float t[32][33];
    const int n0 = blockIdx.x*32, k0 = blockIdx.y*32;
    const int tx = threadIdx.x & 31, tg = threadIdx.x >> 5;   // 256 threads
    #pragma unroll
    for (int i=0;i<4;i++) {
        int r = tg + i*8;
        t[r][tx] = src[(size_t)(k0+r)*N + n0 + tx];
    }
    __syncthreads();
    #pragma unroll
    for (int i=0;i<4;i++) {
        int r = tg + i*8;
        dst[(size_t)(n0+r)*K + k0 + tx] = tf32r(t[tx][r]);
    }
}

// =====================================================================
// TF32 GEMM via ldmatrix + mma.m16n8k8: C = epi((A@B + bias)*alpha)
// A[M][K] row-major (tf32-rounded), Bt[N][K] row-major (transposed,
// rounded weights). 256x128x32 tiles, 8 warps, 64x64 warp tiles,
// 2-stage cp.async double buffering (R4 skeleton).
// blockIdx.z selects (Bt, bias, D, alpha) -> fused QKV.
// OUTMODE: 0 plain [M,N]; 1 head-split. EPI: 1 GELU. ROUND: tf32 out.
// Requires K%32==0, N%128==0.
// =====================================================================
#define STAGE_FLOATS (384*36)                 // A 256*36 + Bt 128*36 = 13824
#define STAGE_BYTES  (STAGE_FLOATS*4)         // 55296
#define GEMM_SMEM_BYTES (256*132*4)           // 135168 >= 2*55296

template<int OUTMODE,int EPI,int ROUND>
__launch_bounds__(256)
__global__ void tgemm_k(const float* __restrict__ A,
                        const float* __restrict__ B0, const float* __restrict__ B1, const float* __restrict__ B2,
                        const float* __restrict__ c0, const float* __restrict__ c1, const float* __restrict__ c2,
                        float* __restrict__ D0, float* __restrict__ D1, float* __restrict__ D2,
                        int M, int N, int K, float a0, float a1, float a2)
{
    extern __shared__ float sm[];
    const uint32_t smBase = (uint32_t)__cvta_generic_to_shared(sm);

    const int z = blockIdx.z;
    const float* Bt   = (z==0) ? B0 : (z==1) ? B1 : B2;
    const float* bias = (z==0) ? c0 : (z==1) ? c1 : c2;
    float*       C    = (z==0) ? D0 : (z==1) ? D1 : D2;
    const float alpha = (z==0) ? a0 : (z==1) ? a1 : a2;

    const int tileM = blockIdx.y * 256;
    const int tileN = blockIdx.x * 128;
    const int tid   = threadIdx.x;
    const int warpId= tid >> 5;
    const int lane  = tid & 31;
    const int wm    = warpId >> 1;      // 0..3 -> m offset wm*64
    const int wn    = warpId & 1;       // 0..1 -> n offset wn*64

    // cp.async thread mapping (16B per thread)
    const int ldRow = tid >> 3;         // 0..31
    const int ldCol = (tid & 7) << 2;   // 0,4,...,28

    const float* aPtr[8];
    #pragma unroll
    for (int t=0;t<8;t++) {
        int gm = tileM + t*32 + ldRow;
        if (gm > M-1) gm = M-1;
        aPtr[t] = A + (size_t)gm*K + ldCol;
    }
    const float* bPtr[4];
    #pragma unroll
    for (int t=0;t<4;t++)
        bPtr[t] = Bt + (size_t)(tileN + t*32 + ldRow)*K + ldCol;

    // ldmatrix per-thread address components
    const int aRowOff = (lane & 7) + ((lane >> 3) & 1) * 8;   // row within 16
    const int aKH     = (lane >> 4) * 4;                      // k half
    const int bNOff   = (lane & 7) + (lane >> 4) * 8;         // n within 16
    const int bKH     = ((lane >> 3) & 1) * 4;

    const uint32_t aAddr0 = smBase + (uint32_t)(((wm*64 + aRowOff)*36 + aKH) * 4);
    const uint32_t bAddr0 = smBase + (uint32_t)((9216 + (wn*64 + bNOff)*36 + bKH) * 4); // 256*36=9216

    float acc[4][8][4];
    #pragma unroll
    for (int i=0;i<4;i++)
        #pragma unroll
        for (int j=0;j<8;j++)
            #pragma unroll
            for (int t=0;t<4;t++) acc[i][j][t] = 0.f;

    auto loadStage = [&](int k0, int st) {
        const uint32_t ab = smBase + (uint32_t)st*STAGE_BYTES;
        const uint32_t bb = ab + 9216u*4u;
        #pragma unroll
        for (int t=0;t<8;t++)
            cpa16(ab + (uint32_t)(((t*32 + ldRow)*36 + ldCol)*4), aPtr[t] + k0);
        #pragma unroll
        for (int t=0;t<4;t++)
            cpa16(bb + (uint32_t)(((t*32 + ldRow)*36 + ldCol)*4), bPtr[t] + k0);
        asm volatile("cp.async.commit_group;" ::: "memory");
    };

    const int NS = K >> 5;
    loadStage(0, 0);

    int buf = 0;
    for (int s = 0; s < NS; s++) {
        if (s + 1 < NS) {
            loadStage((s+1) << 5, buf^1);
            asm volatile("cp.async.wait_group 1;" ::: "memory");
        } else {
            asm volatile("cp.async.wait_group 0;" ::: "memory");
        }
        __syncthreads();

        const uint32_t aS = aAddr0 + (uint32_t)buf*STAGE_BYTES;
        const uint32_t bS = bAddr0 + (uint32_t)buf*STAGE_BYTES;
        #pragma unroll
        for (int ks=0; ks<4; ks++) {
            uint32_t a[4][4], b[4][4];
            #pragma unroll
            for (int mb=0; mb<4; mb++)
                ldsm4(aS + (uint32_t)(mb*16*36*4 + ks*32), a[mb][0], a[mb][1], a[mb][2], a[mb][3]);
            #pragma unroll
            for (int nb=0; nb<4; nb++)
                ldsm4(bS + (uint32_t)(nb*16*36*4 + ks*32), b[nb][0], b[nb][1], b[nb][2], b[nb][3]);
            #pragma unroll
            for (int mb=0; mb<4; mb++)
                #pragma unroll
                for (int j=0; j<8; j++)
                    mma_tf32(acc[mb][j], a[mb][0], a[mb][1], a[mb][2], a[mb][3],
                             b[j>>1][(j&1)*2], b[j>>1][(j&1)*2+1]);
        }
        __syncthreads();
        buf ^= 1;
    }

    // ---- epilogue: stage 256x128 tile in smem (pitch 132), float4 writes ----
    {
        const int r0 = lane >> 2;            // 0..7
        const int cb = 2*(lane & 3);         // 0,2,4,6
        #pragma unroll
        for (int mb=0; mb<4; mb++) {
            #pragma unroll
            for (int j=0; j<8; j++) {
                int row = wm*64 + mb*16 + r0;
                int col = wn*64 + j*8 + cb;
                *reinterpret_cast<float2*>(&sm[row*132 + col])     = make_float2(acc[mb][j][0], acc[mb][j][1]);
                *reinterpret_cast<float2*>(&sm[(row+8)*132 + col]) = make_float2(acc[mb][j][2], acc[mb][j][3]);
            }
        }
    }
    __syncthreads();

    #pragma unroll
    for (int rr=0; rr<2; rr++) {
        const int row = rr*128 + (tid >> 1);
        const int gm  = tileM + row;
        if (gm >= M) continue;
        int b = 0, s = 0;
        if (OUTMODE == 1) { b = gm / SEQ; s = gm - b*SEQ; }
        #pragma unroll
        for (int f=0; f<16; f++) {
            int c  = (tid & 1)*64 + f*4;
            int gn = tileN + c;
            float4 v = *reinterpret_cast<const float4*>(&sm[row*132 + c]);
            v.x = (v.x + bias[gn  ]) * alpha;
            v.y = (v.y + bias[gn+1]) * alpha;
            v.z = (v.z + bias[gn+2]) * alpha;
            v.w = (v.w + bias[gn+3]) * alpha;
            if (EPI == 1) {
                v.x = gelu_exact(v.x); v.y = gelu_exact(v.y);
                v.z = gelu_exact(v.z); v.w = gelu_exact(v.w);
            }
            if (ROUND) {
                v.x = tf32r(v.x); v.y = tf32r(v.y); v.z = tf32r(v.z); v.w = tf32r(v.w);
            }
            if (OUTMODE == 0) {
                *reinterpret_cast<float4*>(&C[(size_t)gm*N + gn]) = v;
            } else {
                int h = gn >> 6, dd = gn & 63;
                size_t orow = (size_t)(b*NHEAD + h)*SEQ + s;
                *reinterpret_cast<float4*>(&C[orow*HDIM + dd]) = v;
            }
        }
    }
}

// =====================================================================
// Fused attention: one CTA per (b,h), 512 threads (16 warps).
// q pre-scaled by 1/8; q,k,v already tf32-rounded.
// =====================================================================
#define ATTN_SMEM_FLOATS (64*KL + SEQP*VL + 64*VL + 64*KL)
#define ATTN_SMEM_BYTES  (ATTN_SMEM_FLOATS*4)

__launch_bounds__(512)
__global__ void attn_k(const float* __restrict__ q, const float* __restrict__ k,
                       const float* __restrict__ v, float* __restrict__ ctx)
{
    extern __shared__ float sm[];
    float* Ksm = sm;
    float* Vsm = Ksm + 64*KL;
    float* QO  = Vsm + SEQP*VL;
    float* Ssm = QO  + 64*VL;

    const int bh = blockIdx.x;
    const int b  = bh / NHEAD;
    const int h  = bh - b*NHEAD;
    const int tid    = threadIdx.x;
    const int warpId = tid >> 5;
    const int lane   = tid & 31;

    const float* qb = q + (size_t)bh*SEQ*HDIM;
    const float* kb = k + (size_t)bh*SEQ*HDIM;
    const float* vb = v + (size_t)bh*SEQ*HDIM;

    for (int idx = tid; idx < SEQP*HDIM; idx += 512) {
        int s = idx >> 6, d = idx & 63;
        Ksm[d*KL + s] = (s < SEQ) ? kb[(size_t)s*HDIM + d] : 0.f;
    }
    for (int idx = tid; idx < SEQP*16; idx += 512) {
        int t = idx >> 4, f = idx & 15;
        float4 val = (t < SEQ) ? *reinterpret_cast<const float4*>(&vb[(size_t)t*HDIM + f*4])
                               : make_float4(0.f,0.f,0.f,0.f);
        *reinterpret_cast<float4*>(&Vsm[t*VL + f*4]) = val;
    }
    __syncthreads();

    for (int s0 = 0; s0 < SEQ; s0 += 64) {
        for (int idx = tid; idx < 64*16; idx += 512) {
            int r = idx >> 4, f = idx & 15;
            int s = s0 + r;
            float4 val = (s < SEQ) ? *reinterpret_cast<const float4*>(&qb[(size_t)s*HDIM + f*4])
                                   : make_float4(0.f,0.f,0.f,0.f);
            *reinterpret_cast<float4*>(&QO[r*VL + f*4]) = val;
        }
        __syncthreads();

        for (int t = warpId; t < 52; t += 16) {
            int mi = t / 13, ni = t - (t/13)*13;
            wmma::fragment<wmma::accumulator, 16, 16, 8, float> sac;
            wmma::fill_fragment(sac, 0.0f);
            #pragma unroll
            for (int ks=0; ks<8; ks++) {
                wmma::fragment<wmma::matrix_a, 16, 16, 8, wmma::precision::tf32, wmma::row_major> af;
                wmma::fragment<wmma::matrix_b, 16, 16, 8, wmma::precision::tf32, wmma::row_major> bf;
                wmma::load_matrix_sync(af, &QO[(mi*16)*VL + ks*8], VL);
                wmma::load_matrix_sync(bf, &Ksm[(ks*8)*KL + ni*16], KL);
                wmma::mma_sync(sac, af, bf, sac);
            }
            wmma::store_matrix_sync(&Ssm[(mi*16)*KL + ni*16], sac, KL, wmma::mem_row_major);
        }
        __syncthreads();

        #pragma unroll
        for (int rr = 0; rr < 4; rr++) {
            int r = warpId*4 + rr;
            float* rowp = &Ssm[r*KL];
            float x[7];
            float m = -1e30f;
            #pragma unroll
            for (int i=0;i<7;i++) {
                int c = lane + i*32;
                x[i] = (c < SEQ) ? rowp[c] : -1e30f;
                m = fmaxf(m, x[i]);
            }
            #pragma unroll
            for (int o=16;o;o>>=1) m = fmaxf(m, __shfl_xor_sync(0xffffffffu, m, o));
            float sum = 0.f;
            #pragma unroll
            for (int i=0;i<7;i++) { x[i] = __expf(x[i] - m); sum += x[i]; }
            #pragma unroll
            for (int o=16;o;o>>=1) sum += __shfl_xor_sync(0xffffffffu, sum, o);
            float inv = 1.f / sum;
            #pragma unroll
            for (int i=0;i<7;i++) {
                int c = lane + i*32;
                if (c < SEQ)       rowp[c] = tf32r(x[i]*inv);
                else if (c < SEQP) rowp[c] = 0.f;
            }
        }
        __syncthreads();

        {
            int mi = warpId >> 2, ni = warpId & 3;
            wmma::fragment<wmma::accumulator, 16, 16, 8, float> oac;
            wmma::fill_fragment(oac, 0.0f);
            #pragma unroll
            for (int ks=0; ks<26; ks++) {
                wmma::fragment<wmma::matrix_a, 16, 16, 8, wmma::precision::tf32, wmma::row_major> af;
                wmma::fragment<wmma::matrix_b, 16, 16, 8, wmma::precision::tf32, wmma::row_major> bf;
                wmma::load_matrix_sync(af, &Ssm[(mi*16)*KL + ks*8], KL);
                wmma::load_matrix_sync(bf, &Vsm[(ks*8)*VL + ni*16], VL);
                wmma::mma_sync(oac, af, bf, oac);
            }
            wmma::store_matrix_sync(&QO[(mi*16)*VL + ni*16], oac, VL, wmma::mem_row_major);
        }
        __syncthreads();

        for (int idx = tid; idx < 64*16; idx += 512) {
            int r = idx >> 4, f = idx & 15;
            int s = s0 + r;
            if (s < SEQ) {
                float4 val = *reinterpret_cast<const float4*>(&QO[r*VL + f*4]);
                val.x=tf32r(val.x); val.y=tf32r(val.y); val.z=tf32r(val.z); val.w=tf32r(val.w);
                *reinterpret_cast<float4*>(&ctx[((size_t)(b*SEQ + s))*DIM + h*HDIM + f*4]) = val;
            }
        }
        __syncthreads();
    }
}

// ---------------- residual + LayerNorm (optional rounded copy) ----------------
__global__ void add_ln_k(const float* __restrict__ x, const float* __restrict__ y,
                         const float* __restrict__ g, const float* __restrict__ be,
                         float* __restrict__ out, float* __restrict__ outR)
{
    const int r = blockIdx.x;
    const float* yr = y + (long)r*DIM;
    const float* xr = x + (long)r*DIM;

    float s = 0.f, sq = 0.f;
    for (int i = threadIdx.x; i < DIM; i += blockDim.x) {
        float t = yr[i]; s += t; sq += t*t;
    }
    __shared__ float red[64];
    #pragma unroll
    for (int o=16;o;o>>=1) { s += __shfl_xor_sync(0xffffffffu, s, o); sq += __shfl_xor_sync(0xffffffffu, sq, o); }
    int w = threadIdx.x >> 5, lane = threadIdx.x & 31;
    if (lane == 0) { red[w] = s; red[w+32] = sq; }
    __syncthreads();
    if (threadIdx.x < 32) {
        int nw = blockDim.x >> 5;
        s  = (threadIdx.x < nw) ? red[threadIdx.x]      : 0.f;
        sq = (threadIdx.x < nw) ? red[threadIdx.x + 32] : 0.f;
        #pragma unroll
        for (int o=16;o;o>>=1) { s += __shfl_xor_sync(0xffffffffu, s, o); sq += __shfl_xor_sync(0xffffffffu, sq, o); }
        if (threadIdx.x == 0) { red[0] = s; red[1] = sq; }
    }
    __syncthreads();
    float mu   = red[0] * (1.f/DIM);
    float var  = red[1] * (1.f/DIM) - mu*mu;
    float rstd = rsqrtf(var + LN_EPS);
    for (int i = threadIdx.x; i < DIM; i += blockDim.x) {
        float val = xr[i] + (yr[i] - mu) * rstd * g[i] + be[i];
        out[(long)r*DIM + i] = val;
        if (outR) outR[(long)r*DIM + i] = tf32r(val);
    }
}

// ---------------- launch ----------------
extern "C" void kernel_launch(void* const* d_in, const int* in_sizes, int n_in,
                              void* d_out, int out_size)
{
    const float* x   = (const float*)d_in[0];
    const float* Wq  = (const float*)d_in[1];
    const float* bq  = (const float*)d_in[2];
    const float* Wk  = (const float*)d_in[3];
    const float* bk  = (const float*)d_in[4];
    const float* Wv  = (const float*)d_in[5];
    const float* bv  = (const float*)d_in[6];
    const float* Wo  = (const float*)d_in[7];
    const float* bo  = (const float*)d_in[8];
    const float* W1  = (const float*)d_in[9];
    const float* b1  = (const float*)d_in[10];
    const float* W2  = (const float*)d_in[11];
    const float* b2  = (const float*)d_in[12];
    const float* g1  = (const float*)d_in[13];
    const float* be1 = (const float*)d_in[14];
    const float* g2  = (const float*)d_in[15];
    const float* be2 = (const float*)d_in[16];
    float* out = (float*)d_out;

    float *q,*k,*v,*ctx,*ao,*x1,*x1r,*xr,*hh,*mlp;
    float *wqT,*wkT,*wvT,*woT,*w1T,*w2T;
    cudaGetSymbolAddress((void**)&q,   g_q);
    cudaGetSymbolAddress((void**)&k,   g_k);
    cudaGetSymbolAddress((void**)&v,   g_v);
    cudaGetSymbolAddress((void**)&ctx, g_ctx);
    cudaGetSymbolAddress((void**)&ao,  g_ao);
    cudaGetSymbolAddress((void**)&x1,  g_x1);
    cudaGetSymbolAddress((void**)&x1r, g_x1r);
    cudaGetSymbolAddress((void**)&xr,  g_xr);
    cudaGetSymbolAddress((void**)&hh,  g_h);
    cudaGetSymbolAddress((void**)&mlp, g_mlp);
    cudaGetSymbolAddress((void**)&wqT, g_wqT);
    cudaGetSymbolAddress((void**)&wkT, g_wkT);
    cudaGetSymbolAddress((void**)&wvT, g_wvT);
    cudaGetSymbolAddress((void**)&woT, g_woT);
    cudaGetSymbolAddress((void**)&w1T, g_w1T);
    cudaGetSymbolAddress((void**)&w2T, g_w2T);

    cudaFuncSetAttribute(tgemm_k<1,0,1>, cudaFuncAttributeMaxDynamicSharedMemorySize, GEMM_SMEM_BYTES);
    cudaFuncSetAttribute(tgemm_k<0,0,0>, cudaFuncAttributeMaxDynamicSharedMemorySize, GEMM_SMEM_BYTES);
    cudaFuncSetAttribute(tgemm_k<0,1,1>, cudaFuncAttributeMaxDynamicSharedMemorySize, GEMM_SMEM_BYTES);
    cudaFuncSetAttribute(attn_k,         cudaFuncAttributeMaxDynamicSharedMemorySize, ATTN_SMEM_BYTES);

    // --- pre-pass: transpose+round weights, round x ---
    {
        dim3 tg(DIM/32, DIM/32);
        troundT_k<<<tg, 256>>>(Wq, wqT, DIM, DIM);
        troundT_k<<<tg, 256>>>(Wk, wkT, DIM, DIM);
        troundT_k<<<tg, 256>>>(Wv, wvT, DIM, DIM);
        troundT_k<<<tg, 256>>>(Wo, woT, DIM, DIM);
        dim3 tg1(HID/32, DIM/32);
        troundT_k<<<tg1, 256>>>(W1, w1T, DIM, HID);
        dim3 tg2(DIM/32, HID/32);
        troundT_k<<<tg2, 256>>>(W2, w2T, HID, DIM);
        int n = TOK*DIM/4;
        round_k<<<(n+255)/256, 256>>>(x, xr, n);
    }

    const int mtiles = (TOK + 255)/256;   // 50

    // --- fused QKV projection ---
    {
        dim3 grid(DIM/128, mtiles, 3);
        tgemm_k<1,0,1><<<grid, 256, GEMM_SMEM_BYTES>>>(xr, wqT, wkT, wvT, bq, bk, bv,
                                                       q, k, v, TOK, DIM, DIM,
                                                       0.125f, 1.0f, 1.0f);
    }

    // --- fused attention -> ctx (rounded) ---
    attn_k<<<BH, 512, ATTN_SMEM_BYTES>>>(q, k, v, ctx);

    // --- attn_out = ctx @ Wo + bo ---
    {
        dim3 grid(DIM/128, mtiles, 1);
        tgemm_k<0,0,0><<<grid, 256, GEMM_SMEM_BYTES>>>(ctx, woT, woT, woT, bo, bo, bo,
                                                       ao, ao, ao, TOK, DIM, DIM,
                                                       1.0f, 1.0f, 1.0f);
    }

    // --- x1 = x + LN(attn_out); rounded copy for MLP1 ---
    add_ln_k<<<TOK, 256>>>(x, ao, g1, be1, x1, x1r);

    // --- h = gelu(x1 @ W1 + b1) (rounded) ---
    {
        dim3 grid(HID/128, mtiles, 1);
        tgemm_k<0,1,1><<<grid, 256, GEMM_SMEM_BYTES>>>(x1r, w1T, w1T, w1T, b1, b1, b1,
                                                       hh, hh, hh, TOK, HID, DIM,
                                                       1.0f, 1.0f, 1.0f);
    }

    // --- mlp = h @ W2 + b2 ---
    {
        dim3 grid(DIM/128, mtiles, 1);
        tgemm_k<0,0,0><<<grid, 256, GEMM_SMEM_BYTES>>>(hh, w2T, w2T, w2T, b2, b2, b2,
                                                       mlp, mlp, mlp, TOK, DIM, HID,
                                                       1.0f, 1.0f, 1.0f);
    }

    // --- out = x1 + LN(mlp) ---
    add_ln_k<<<TOK, 256>>>(x1, mlp, g2, be2, out, nullptr);
}

// round 8
// speedup vs baseline: 1.8765x; 1.0824x over previous
#include <cuda_runtime.h>
#include <cuda_bf16.h>
#include <mma.h>
#include <math.h>
#include <stdint.h>

using namespace nvcuda;

// ---------------- problem constants ----------------
#define BATCH   64
#define SEQ     197
#define TOK     (BATCH*SEQ)      // 12608
#define DIM     768
#define NHEAD   12
#define HDIM    64
#define HID     3072
#define BH      (BATCH*NHEAD)    // 768
#define LN_EPS  1e-6f

// padded attention dims
#define SEQP    208
#define KL      212              // pitch for t-contiguous rows (S, V^T)
#define VL      68               // pitch for d-contiguous rows (Q, K)

// ---------------- scratch (device globals) ----------------
__device__ float g_q  [(long)BH*SEQ*HDIM];
__device__ float g_k  [(long)BH*SEQ*HDIM];
__device__ float g_v  [(long)BH*SEQ*HDIM];
__device__ float g_ctx[(long)TOK*DIM];
__device__ float g_ao [(long)TOK*DIM];
__device__ float g_x1 [(long)TOK*DIM];
__device__ float g_x1r[(long)TOK*DIM];
__device__ float g_xr [(long)TOK*DIM];
__device__ float g_h  [(long)TOK*HID];
__device__ float g_mlp[(long)TOK*DIM];
// transposed + tf32-rounded weights: [N][K]
__device__ float g_wqT[DIM*DIM];
__device__ float g_wkT[DIM*DIM];
__device__ float g_wvT[DIM*DIM];
__device__ float g_woT[DIM*DIM];
__device__ float g_w1T[(long)HID*DIM];
__device__ float g_w2T[(long)DIM*HID];

__device__ __forceinline__ float tf32r(float x) { return wmma::__float_to_tf32(x); }
__device__ __forceinline__ float gelu_exact(float v) {
    return 0.5f * v * (1.f + erff(v * 0.70710678118654752f));
}
__device__ __forceinline__ void cpa16(uint32_t dst, const float* src) {
    asm volatile("cp.async.cg.shared.global [%0], [%1], 16;" :: "r"(dst), "l"(src) : "memory");
}
__device__ __forceinline__ void ldsm4(uint32_t addr, uint32_t& r0, uint32_t& r1,
                                      uint32_t& r2, uint32_t& r3) {
    asm volatile("ldmatrix.sync.aligned.m8n8.x4.shared.b16 {%0,%1,%2,%3}, [%4];"
                 : "=r"(r0), "=r"(r1), "=r"(r2), "=r"(r3) : "r"(addr));
}
__device__ __forceinline__ void mma_tf32(float* c, uint32_t a0, uint32_t a1,
                                         uint32_t a2, uint32_t a3,
                                         uint32_t b0, uint32_t b1) {
    asm volatile("mma.sync.aligned.m16n8k8.row.col.f32.tf32.tf32.f32 "
                 "{%0,%1,%2,%3}, {%4,%5,%6,%7}, {%8,%9}, {%0,%1,%2,%3};"
                 : "+f"(c[0]), "+f"(c[1]), "+f"(c[2]), "+f"(c[3])
                 : "r"(a0), "r"(a1), "r"(a2), "r"(a3), "r"(b0), "r"(b1));
}

// ---------------- tf32 RN rounding kernel (float4) ----------------
__global__ void round_k(const float* __restrict__ src, float* __restrict__ dst, int n4)
{
    int i = blockIdx.x*blockDim.x + threadIdx.x;
    if (i < n4) {
        float4 v = reinterpret_cast<const float4*>(src)[i];
        v.x = tf32r(v.x); v.y = tf32r(v.y); v.z = tf32r(v.z); v.w = tf32r(v.w);
        reinterpret_cast<float4*>(dst)[i] = v;
    }
}

// ---------------- transpose + tf32-round: src[K][N] -> dst[N][K] ----------------
__global__ void troundT_k(const float* __restrict__ src, float* __restrict__ dst,
                          int K, int N)
{
    __shared__ float t[32][33];
    const int n0 = blockIdx.x*32, k0 = blockIdx.y*32;
    const int tx = threadIdx.x & 31, tg = threadIdx.x >> 5;   // 256 threads
    #pragma unroll
    for (int i=0;i<4;i++) {
        int r = tg + i*8;
        t[r][tx] = src[(size_t)(k0+r)*N + n0 + tx];
    }
    __syncthreads();
    #pragma unroll
    for (int i=0;i<4;i++) {
        int r = tg + i*8;
        dst[(size_t)(n0+r)*K + k0 + tx] = tf32r(t[tx][r]);
    }
}

// =====================================================================
// TF32 GEMM via ldmatrix + mma.m16n8k8 (unchanged from R7, proven)
// =====================================================================
#define STAGE_FLOATS (384*36)
#define STAGE_BYTES  (STAGE_FLOATS*4)
#define GEMM_SMEM_BYTES (256*132*4)

template<int OUTMODE,int EPI,int ROUND>
__launch_bounds__(256)
__global__ void tgemm_k(const float* __restrict__ A,
                        const float* __restrict__ B0, const float* __restrict__ B1, const float* __restrict__ B2,
                        const float* __restrict__ c0, const float* __restrict__ c1, const float* __restrict__ c2,
                        float* __restrict__ D0, float* __restrict__ D1, float* __restrict__ D2,
                        int M, int N, int K, float a0, float a1, float a2)
{
    extern __shared__ float sm[];
    const uint32_t smBase = (uint32_t)__cvta_generic_to_shared(sm);

    const int z = blockIdx.z;
    const float* Bt   = (z==0) ? B0 : (z==1) ? B1 : B2;
    const float* bias = (z==0) ? c0 : (z==1) ? c1 : c2;
    float*       C    = (z==0) ? D0 : (z==1) ? D1 : D2;
    const float alpha = (z==0) ? a0 : (z==1) ? a1 : a2;

    const int tileM = blockIdx.y * 256;
    const int tileN = blockIdx.x * 128;
    const int tid   = threadIdx.x;
    const int warpId= tid >> 5;
    const int lane  = tid & 31;
    const int wm    = warpId >> 1;
    const int wn    = warpId & 1;

    const int ldRow = tid >> 3;
    const int ldCol = (tid & 7) << 2;

    const float* aPtr[8];
    #pragma unroll
    for (int t=0;t<8;t++) {
        int gm = tileM + t*32 + ldRow;
        if (gm > M-1) gm = M-1;
        aPtr[t] = A + (size_t)gm*K + ldCol;
    }
    const float* bPtr[4];
    #pragma unroll
    for (int t=0;t<4;t++)
        bPtr[t] = Bt + (size_t)(tileN + t*32 + ldRow)*K + ldCol;

    const int aRowOff = (lane & 7) + ((lane >> 3) & 1) * 8;
    const int aKH     = (lane >> 4) * 4;
    const int bNOff   = (lane & 7) + (lane >> 4) * 8;
    const int bKH     = ((lane >> 3) & 1) * 4;

    const uint32_t aAddr0 = smBase + (uint32_t)(((wm*64 + aRowOff)*36 + aKH) * 4);
    const uint32_t bAddr0 = smBase + (uint32_t)((9216 + (wn*64 + bNOff)*36 + bKH) * 4);

    float acc[4][8][4];
    #pragma unroll
    for (int i=0;i<4;i++)
        #pragma unroll
        for (int j=0;j<8;j++)
            #pragma unroll
            for (int t=0;t<4;t++) acc[i][j][t] = 0.f;

    auto loadStage = [&](int k0, int st) {
        const uint32_t ab = smBase + (uint32_t)st*STAGE_BYTES;
        const uint32_t bb = ab + 9216u*4u;
        #pragma unroll
        for (int t=0;t<8;t++)
            cpa16(ab + (uint32_t)(((t*32 + ldRow)*36 + ldCol)*4), aPtr[t] + k0);
        #pragma unroll
        for (int t=0;t<4;t++)
            cpa16(bb + (uint32_t)(((t*32 + ldRow)*36 + ldCol)*4), bPtr[t] + k0);
        asm volatile("cp.async.commit_group;" ::: "memory");
    };

    const int NS = K >> 5;
    loadStage(0, 0);

    int buf = 0;
    for (int s = 0; s < NS; s++) {
        if (s + 1 < NS) {
            loadStage((s+1) << 5, buf^1);
            asm volatile("cp.async.wait_group 1;" ::: "memory");
        } else {
            asm volatile("cp.async.wait_group 0;" ::: "memory");
        }
        __syncthreads();

        const uint32_t aS = aAddr0 + (uint32_t)buf*STAGE_BYTES;
        const uint32_t bS = bAddr0 + (uint32_t)buf*STAGE_BYTES;
        #pragma unroll
        for (int ks=0; ks<4; ks++) {
            uint32_t a[4][4], b[4][4];
            #pragma unroll
            for (int mb=0; mb<4; mb++)
                ldsm4(aS + (uint32_t)(mb*16*36*4 + ks*32), a[mb][0], a[mb][1], a[mb][2], a[mb][3]);
            #pragma unroll
            for (int nb=0; nb<4; nb++)
                ldsm4(bS + (uint32_t)(nb*16*36*4 + ks*32), b[nb][0], b[nb][1], b[nb][2], b[nb][3]);
            #pragma unroll
            for (int mb=0; mb<4; mb++)
                #pragma unroll
                for (int j=0; j<8; j++)
                    mma_tf32(acc[mb][j], a[mb][0], a[mb][1], a[mb][2], a[mb][3],
                             b[j>>1][(j&1)*2], b[j>>1][(j&1)*2+1]);
        }
        __syncthreads();
        buf ^= 1;
    }

    {
        const int r0 = lane >> 2;
        const int cb = 2*(lane & 3);
        #pragma unroll
        for (int mb=0; mb<4; mb++) {
            #pragma unroll
            for (int j=0; j<8; j++) {
                int row = wm*64 + mb*16 + r0;
                int col = wn*64 + j*8 + cb;
                *reinterpret_cast<float2*>(&sm[row*132 + col])     = make_float2(acc[mb][j][0], acc[mb][j][1]);
                *reinterpret_cast<float2*>(&sm[(row+8)*132 + col]) = make_float2(acc[mb][j][2], acc[mb][j][3]);
            }
        }
    }
    __syncthreads();

    #pragma unroll
    for (int rr=0; rr<2; rr++) {
        const int row = rr*128 + (tid >> 1);
        const int gm  = tileM + row;
        if (gm >= M) continue;
        int b = 0, s = 0;
        if (OUTMODE == 1) { b = gm / SEQ; s = gm - b*SEQ; }
        #pragma unroll
        for (int f=0; f<16; f++) {
            int c  = (tid & 1)*64 + f*4;
            int gn = tileN + c;
            float4 v = *reinterpret_cast<const float4*>(&sm[row*132 + c]);
            v.x = (v.x + bias[gn  ]) * alpha;
            v.y = (v.y + bias[gn+1]) * alpha;
            v.z = (v.z + bias[gn+2]) * alpha;
            v.w = (v.w + bias[gn+3]) * alpha;
            if (EPI == 1) {
                v.x = gelu_exact(v.x); v.y = gelu_exact(v.y);
                v.z = gelu_exact(v.z); v.w = gelu_exact(v.w);
            }
            if (ROUND) {
                v.x = tf32r(v.x); v.y = tf32r(v.y); v.z = tf32r(v.z); v.w = tf32r(v.w);
            }
            if (OUTMODE == 0) {
                *reinterpret_cast<float4*>(&C[(size_t)gm*N + gn]) = v;
            } else {
                int h = gn >> 6, dd = gn & 63;
                size_t orow = (size_t)(b*NHEAD + h)*SEQ + s;
                *reinterpret_cast<float4*>(&C[orow*HDIM + dd]) = v;
            }
        }
    }
}

// =====================================================================
// Fused attention via ldmatrix + mma.m16n8k8.
// One CTA per (b,h), 512 threads (16 warps).
// Layouts: Ksm [SEQP][VL] (t,d d-contig); Vsm [HDIM][KL] (d,t t-contig,
// i.e. V^T); QO [64][VL]; Ssm [64][KL].
// q pre-scaled by 1/8; q,k,v already tf32-rounded.
// =====================================================================
#define OFF_K   0
#define OFF_V   (SEQP*VL)                 // 14144
#define OFF_QO  (OFF_V + 64*KL)           // 27712
#define OFF_S   (OFF_QO + 64*VL)          // 32064
#define ATTN_SMEM_FLOATS (OFF_S + 64*KL)  // 45632
#define ATTN_SMEM_BYTES  (ATTN_SMEM_FLOATS*4)

__launch_bounds__(512)
__global__ void attn_k(const float* __restrict__ q, const float* __restrict__ k,
                       const float* __restrict__ v, float* __restrict__ ctx)
{
    extern __shared__ float sm[];
    const uint32_t smBase = (uint32_t)__cvta_generic_to_shared(sm);
    float* Ksm = sm + OFF_K;
    float* Vsm = sm + OFF_V;
    float* QO  = sm + OFF_QO;
    float* Ssm = sm + OFF_S;

    const int bh = blockIdx.x;
    const int b  = bh / NHEAD;
    const int h  = bh - b*NHEAD;
    const int tid    = threadIdx.x;
    const int warpId = tid >> 5;
    const int lane   = tid & 31;

    const float* qb = q + (size_t)bh*SEQ*HDIM;
    const float* kb = k + (size_t)bh*SEQ*HDIM;
    const float* vb = v + (size_t)bh*SEQ*HDIM;

    // ldmatrix lane constants (same mapping as GEMM, bench-validated)
    const int aRowOff = (lane & 7) + ((lane >> 3) & 1) * 8;
    const int aKH     = (lane >> 4) * 4;
    const int bNOff   = (lane & 7) + (lane >> 4) * 8;
    const int bKH     = ((lane >> 3) & 1) * 4;
    const int r0 = lane >> 2;
    const int cb = 2*(lane & 3);

    // ---- K direct [t][d] (float4), zero-pad t>=197 ----
    for (int idx = tid; idx < SEQP*16; idx += 512) {
        int t = idx >> 4, f = idx & 15;
        float4 val = (t < SEQ) ? *reinterpret_cast<const float4*>(&kb[(size_t)t*HDIM + f*4])
                               : make_float4(0.f,0.f,0.f,0.f);
        *reinterpret_cast<float4*>(&Ksm[t*VL + f*4]) = val;
    }
    // ---- V transposed [d][t], zero-pad t>=197 ----
    for (int idx = tid; idx < SEQP*HDIM; idx += 512) {
        int t = idx >> 6, d = idx & 63;
        Vsm[d*KL + t] = (t < SEQ) ? vb[(size_t)t*HDIM + d] : 0.f;
    }
    __syncthreads();

    for (int s0 = 0; s0 < SEQ; s0 += 64) {
        // ---- Q tile ----
        for (int idx = tid; idx < 64*16; idx += 512) {
            int r = idx >> 4, f = idx & 15;
            int s = s0 + r;
            float4 val = (s < SEQ) ? *reinterpret_cast<const float4*>(&qb[(size_t)s*HDIM + f*4])
                                   : make_float4(0.f,0.f,0.f,0.f);
            *reinterpret_cast<float4*>(&QO[r*VL + f*4]) = val;
        }
        __syncthreads();

        // ---- scores: 4 m-tiles x 13 n-tiles, ldmatrix + mma ----
        for (int t = warpId; t < 52; t += 16) {
            int mi = t / 13, ni = t - (t/13)*13;
            float c0[4] = {0.f,0.f,0.f,0.f}, c1[4] = {0.f,0.f,0.f,0.f};
            const uint32_t aAddr = smBase + (uint32_t)((OFF_QO + (mi*16 + aRowOff)*VL + aKH)*4);
            const uint32_t bAddr = smBase + (uint32_t)((OFF_K  + (ni*16 + bNOff)*VL + bKH)*4);
            #pragma unroll
            for (int ks=0; ks<8; ks++) {
                uint32_t a0,a1,a2,a3, b0,b1,b2,b3;
                ldsm4(aAddr + ks*32, a0,a1,a2,a3);
                ldsm4(bAddr + ks*32, b0,b1,b2,b3);
                mma_tf32(c0, a0,a1,a2,a3, b0,b1);
                mma_tf32(c1, a0,a1,a2,a3, b2,b3);
            }
            {
                int row = mi*16 + r0, col = ni*16 + cb;
                *reinterpret_cast<float2*>(&Ssm[row*KL + col])         = make_float2(c0[0], c0[1]);
                *reinterpret_cast<float2*>(&Ssm[(row+8)*KL + col])     = make_float2(c0[2], c0[3]);
                *reinterpret_cast<float2*>(&Ssm[row*KL + col + 8])     = make_float2(c1[0], c1[1]);
                *reinterpret_cast<float2*>(&Ssm[(row+8)*KL + col + 8]) = make_float2(c1[2], c1[3]);
            }
        }
        __syncthreads();

        // ---- softmax: 4 rows per warp ----
        #pragma unroll
        for (int rr = 0; rr < 4; rr++) {
            int r = warpId*4 + rr;
            float* rowp = &Ssm[r*KL];
            float x[7];
            float m = -1e30f;
            #pragma unroll
            for (int i=0;i<7;i++) {
                int c = lane + i*32;
                x[i] = (c < SEQ) ? rowp[c] : -1e30f;
                m = fmaxf(m, x[i]);
            }
            #pragma unroll
            for (int o=16;o;o>>=1) m = fmaxf(m, __shfl_xor_sync(0xffffffffu, m, o));
            float sum = 0.f;
            #pragma unroll
            for (int i=0;i<7;i++) { x[i] = __expf(x[i] - m); sum += x[i]; }
            #pragma unroll
            for (int o=16;o;o>>=1) sum += __shfl_xor_sync(0xffffffffu, sum, o);
            float inv = 1.f / sum;
            #pragma unroll
            for (int i=0;i<7;i++) {
                int c = lane + i*32;
                if (c < SEQ)       rowp[c] = tf32r(x[i]*inv);
                else if (c < SEQP) rowp[c] = 0.f;
            }
        }
        __syncthreads();

        // ---- O = P @ V^T-layout: one 16x16 tile per warp ----
        {
            int mi = warpId >> 2, ni = warpId & 3;
            float c0[4] = {0.f,0.f,0.f,0.f}, c1[4] = {0.f,0.f,0.f,0.f};
            const uint32_t aAddr = smBase + (uint32_t)((OFF_S + (mi*16 + aRowOff)*KL + aKH)*4);
            const uint32_t bAddr = smBase + (uint32_t)((OFF_V + (ni*16 + bNOff)*KL + bKH)*4);
            #pragma unroll
            for (int ks=0; ks<26; ks++) {
                uint32_t a0,a1,a2,a3, b0,b1,b2,b3;
                ldsm4(aAddr + ks*32, a0,a1,a2,a3);
                ldsm4(bAddr + ks*32, b0,b1,b2,b3);
                mma_tf32(c0, a0,a1,a2,a3, b0,b1);
                mma_tf32(c1, a0,a1,a2,a3, b2,b3);
            }
            __syncthreads();   // Ssm reads done before QO overwrite? QO != Ssm, but QO holds Q still being read? No: scores done. Protect nothing; keep for safety of QO reuse ordering.
            {
                int row = mi*16 + r0, col = ni*16 + cb;
                *reinterpret_cast<float2*>(&QO[row*VL + col])         = make_float2(c0[0], c0[1]);
                *reinterpret_cast<float2*>(&QO[(row+8)*VL + col])     = make_float2(c0[2], c0[3]);
                *reinterpret_cast<float2*>(&QO[row*VL + col + 8])     = make_float2(c1[0], c1[1]);
                *reinterpret_cast<float2*>(&QO[(row+8)*VL + col + 8]) = make_float2(c1[2], c1[3]);
            }
        }
        __syncthreads();

        // ---- write ctx rows (rounded) ----
        for (int idx = tid; idx < 64*16; idx += 512) {
            int r = idx >> 4, f = idx & 15;
            int s = s0 + r;
            if (s < SEQ) {
                float4 val = *reinterpret_cast<const float4*>(&QO[r*VL + f*4]);
                val.x=tf32r(val.x); val.y=tf32r(val.y); val.z=tf32r(val.z); val.w=tf32r(val.w);
                *reinterpret_cast<float4*>(&ctx[((size_t)(b*SEQ + s))*DIM + h*HDIM + f*4]) = val;
            }
        }
        __syncthreads();
    }
}

// ---------------- residual + LayerNorm (optional rounded copy) ----------------
__global__ void add_ln_k(const float* __restrict__ x, const float* __restrict__ y,
                         const float* __restrict__ g, const float* __restrict__ be,
                         float* __restrict__ out, float* __restrict__ outR)
{
    const int r = blockIdx.x;
    const float* yr = y + (long)r*DIM;
    const float* xr = x + (long)r*DIM;

    float s = 0.f, sq = 0.f;
    for (int i = threadIdx.x; i < DIM; i += blockDim.x) {
        float t = yr[i]; s += t; sq += t*t;
    }
    __shared__ float red[64];
    #pragma unroll
    for (int o=16;o;o>>=1) { s += __shfl_xor_sync(0xffffffffu, s, o); sq += __shfl_xor_sync(0xffffffffu, sq, o); }
    int w = threadIdx.x >> 5, lane = threadIdx.x & 31;
    if (lane == 0) { red[w] = s; red[w+32] = sq; }
    __syncthreads();
    if (threadIdx.x < 32) {
        int nw = blockDim.x >> 5;
        s  = (threadIdx.x < nw) ? red[threadIdx.x]      : 0.f;
        sq = (threadIdx.x < nw) ? red[threadIdx.x + 32] : 0.f;
        #pragma unroll
        for (int o=16;o;o>>=1) { s += __shfl_xor_sync(0xffffffffu, s, o); sq += __shfl_xor_sync(0xffffffffu, sq, o); }
        if (threadIdx.x == 0) { red[0] = s; red[1] = sq; }
    }
    __syncthreads();
    float mu   = red[0] * (1.f/DIM);
    float var  = red[1] * (1.f/DIM) - mu*mu;
    float rstd = rsqrtf(var + LN_EPS);
    for (int i = threadIdx.x; i < DIM; i += blockDim.x) {
        float val = xr[i] + (yr[i] - mu) * rstd * g[i] + be[i];
        out[(long)r*DIM + i] = val;
        if (outR) outR[(long)r*DIM + i] = tf32r(val);
    }
}

// ---------------- launch ----------------
extern "C" void kernel_launch(void* const* d_in, const int* in_sizes, int n_in,
                              void* d_out, int out_size)
{
    const float* x   = (const float*)d_in[0];
    const float* Wq  = (const float*)d_in[1];
    const float* bq  = (const float*)d_in[2];
    const float* Wk  = (const float*)d_in[3];
    const float* bk  = (const float*)d_in[4];
    const float* Wv  = (const float*)d_in[5];
    const float* bv  = (const float*)d_in[6];
    const float* Wo  = (const float*)d_in[7];
    const float* bo  = (const float*)d_in[8];
    const float* W1  = (const float*)d_in[9];
    const float* b1  = (const float*)d_in[10];
    const float* W2  = (const float*)d_in[11];
    const float* b2  = (const float*)d_in[12];
    const float* g1  = (const float*)d_in[13];
    const float* be1 = (const float*)d_in[14];
    const float* g2  = (const float*)d_in[15];
    const float* be2 = (const float*)d_in[16];
    float* out = (float*)d_out;

    float *q,*k,*v,*ctx,*ao,*x1,*x1r,*xr,*hh,*mlp;
    float *wqT,*wkT,*wvT,*woT,*w1T,*w2T;
    cudaGetSymbolAddress((void**)&q,   g_q);
    cudaGetSymbolAddress((void**)&k,   g_k);
    cudaGetSymbolAddress((void**)&v,   g_v);
    cudaGetSymbolAddress((void**)&ctx, g_ctx);
    cudaGetSymbolAddress((void**)&ao,  g_ao);
    cudaGetSymbolAddress((void**)&x1,  g_x1);
    cudaGetSymbolAddress((void**)&x1r, g_x1r);
    cudaGetSymbolAddress((void**)&xr,  g_xr);
    cudaGetSymbolAddress((void**)&hh,  g_h);
    cudaGetSymbolAddress((void**)&mlp, g_mlp);
    cudaGetSymbolAddress((void**)&wqT, g_wqT);
    cudaGetSymbolAddress((void**)&wkT, g_wkT);
    cudaGetSymbolAddress((void**)&wvT, g_wvT);
    cudaGetSymbolAddress((void**)&woT, g_woT);
    cudaGetSymbolAddress((void**)&w1T, g_w1T);
    cudaGetSymbolAddress((void**)&w2T, g_w2T);

    cudaFuncSetAttribute(tgemm_k<1,0,1>, cudaFuncAttributeMaxDynamicSharedMemorySize, GEMM_SMEM_BYTES);
    cudaFuncSetAttribute(tgemm_k<0,0,0>, cudaFuncAttributeMaxDynamicSharedMemorySize, GEMM_SMEM_BYTES);
    cudaFuncSetAttribute(tgemm_k<0,1,1>, cudaFuncAttributeMaxDynamicSharedMemorySize, GEMM_SMEM_BYTES);
    cudaFuncSetAttribute(attn_k,         cudaFuncAttributeMaxDynamicSharedMemorySize, ATTN_SMEM_BYTES);

    // --- pre-pass: transpose+round weights, round x ---
    {
        dim3 tg(DIM/32, DIM/32);
        troundT_k<<<tg, 256>>>(Wq, wqT, DIM, DIM);
        troundT_k<<<tg, 256>>>(Wk, wkT, DIM, DIM);
        troundT_k<<<tg, 256>>>(Wv, wvT, DIM, DIM);
        troundT_k<<<tg, 256>>>(Wo, woT, DIM, DIM);
        dim3 tg1(HID/32, DIM/32);
        troundT_k<<<tg1, 256>>>(W1, w1T, DIM, HID);
        dim3 tg2(DIM/32, HID/32);
        troundT_k<<<tg2, 256>>>(W2, w2T, HID, DIM);
        int n = TOK*DIM/4;
        round_k<<<(n+255)/256, 256>>>(x, xr, n);
    }

    const int mtiles = (TOK + 255)/256;   // 50

    // --- fused QKV projection ---
    {
        dim3 grid(DIM/128, mtiles, 3);
        tgemm_k<1,0,1><<<grid, 256, GEMM_SMEM_BYTES>>>(xr, wqT, wkT, wvT, bq, bk, bv,
                                                       q, k, v, TOK, DIM, DIM,
                                                       0.125f, 1.0f, 1.0f);
    }

    // --- fused attention -> ctx (rounded) ---
    attn_k<<<BH, 512, ATTN_SMEM_BYTES>>>(q, k, v, ctx);

    // --- attn_out = ctx @ Wo + bo ---
    {
        dim3 grid(DIM/128, mtiles, 1);
        tgemm_k<0,0,0><<<grid, 256, GEMM_SMEM_BYTES>>>(ctx, woT, woT, woT, bo, bo, bo,
                                                       ao, ao, ao, TOK, DIM, DIM,
                                                       1.0f, 1.0f, 1.0f);
    }

    // --- x1 = x + LN(attn_out); rounded copy for MLP1 ---
    add_ln_k<<<TOK, 256>>>(x, ao, g1, be1, x1, x1r);

    // --- h = gelu(x1 @ W1 + b1) (rounded) ---
    {
        dim3 grid(HID/128, mtiles, 1);
        tgemm_k<0,1,1><<<grid, 256, GEMM_SMEM_BYTES>>>(x1r, w1T, w1T, w1T, b1, b1, b1,
                                                       hh, hh, hh, TOK, HID, DIM,
                                                       1.0f, 1.0f, 1.0f);
    }

    // --- mlp = h @ W2 + b2 ---
    {
        dim3 grid(DIM/128, mtiles, 1);
        tgemm_k<0,0,0><<<grid, 256, GEMM_SMEM_BYTES>>>(hh, w2T, w2T, w2T, b2, b2, b2,
                                                       mlp, mlp, mlp, TOK, DIM, HID,
                                                       1.0f, 1.0f, 1.0f);
    }

    // --- out = x1 + LN(mlp) ---
    add_ln_k<<<TOK, 256>>>(x1, mlp, g2, be2, out, nullptr);
}

// round 9
// speedup vs baseline: 1.9189x; 1.0226x over previous
#include <cuda_runtime.h>
#include <cuda_bf16.h>
#include <mma.h>
#include <math.h>
#include <stdint.h>

using namespace nvcuda;

// ---------------- problem constants ----------------
#define BATCH   64
#define SEQ     197
#define TOK     (BATCH*SEQ)      // 12608
#define DIM     768
#define NHEAD   12
#define HDIM    64
#define HID     3072
#define BH      (BATCH*NHEAD)    // 768
#define LN_EPS  1e-6f

// padded attention dims
#define SEQP    208
#define KL      212              // pitch for t-contiguous rows (S, V^T)
#define VL      68               // pitch for d-contiguous rows (Q, K)

// ---------------- scratch (device globals) ----------------
__device__ float g_q  [(long)BH*SEQ*HDIM];
__device__ float g_k  [(long)BH*SEQ*HDIM];
__device__ float g_v  [(long)BH*SEQ*HDIM];
__device__ float g_ctx[(long)TOK*DIM];
__device__ float g_ao [(long)TOK*DIM];
__device__ float g_x1 [(long)TOK*DIM];
__device__ float g_x1r[(long)TOK*DIM];
__device__ float g_xr [(long)TOK*DIM];
__device__ float g_h  [(long)TOK*HID];
__device__ float g_mlp[(long)TOK*DIM];
// transposed + tf32-rounded weights: [N][K]
__device__ float g_wqT[DIM*DIM];
__device__ float g_wkT[DIM*DIM];
__device__ float g_wvT[DIM*DIM];
__device__ float g_woT[DIM*DIM];
__device__ float g_w1T[(long)HID*DIM];
__device__ float g_w2T[(long)DIM*HID];

__device__ __forceinline__ float tf32r(float x) { return wmma::__float_to_tf32(x); }
__device__ __forceinline__ float gelu_exact(float v) {
    return 0.5f * v * (1.f + erff(v * 0.70710678118654752f));
}
__device__ __forceinline__ void cpa16(uint32_t dst, const float* src) {
    asm volatile("cp.async.cg.shared.global [%0], [%1], 16;" :: "r"(dst), "l"(src) : "memory");
}
__device__ __forceinline__ void ldsm4(uint32_t addr, uint32_t& r0, uint32_t& r1,
                                      uint32_t& r2, uint32_t& r3) {
    asm volatile("ldmatrix.sync.aligned.m8n8.x4.shared.b16 {%0,%1,%2,%3}, [%4];"
                 : "=r"(r0), "=r"(r1), "=r"(r2), "=r"(r3) : "r"(addr));
}
__device__ __forceinline__ void mma_tf32(float* c, uint32_t a0, uint32_t a1,
                                         uint32_t a2, uint32_t a3,
                                         uint32_t b0, uint32_t b1) {
    asm volatile("mma.sync.aligned.m16n8k8.row.col.f32.tf32.tf32.f32 "
                 "{%0,%1,%2,%3}, {%4,%5,%6,%7}, {%8,%9}, {%0,%1,%2,%3};"
                 : "+f"(c[0]), "+f"(c[1]), "+f"(c[2]), "+f"(c[3])
                 : "r"(a0), "r"(a1), "r"(a2), "r"(a3), "r"(b0), "r"(b1));
}

// ---------------- tf32 RN rounding kernel (float4) ----------------
__global__ void round_k(const float* __restrict__ src, float* __restrict__ dst, int n4)
{
    int i = blockIdx.x*blockDim.x + threadIdx.x;
    if (i < n4) {
        float4 v = reinterpret_cast<const float4*>(src)[i];
        v.x = tf32r(v.x); v.y = tf32r(v.y); v.z = tf32r(v.z); v.w = tf32r(v.w);
        reinterpret_cast<float4*>(dst)[i] = v;
    }
}

// ---------------- transpose + tf32-round: src[K][N] -> dst[N][K] ----------------
__global__ void troundT_k(const float* __restrict__ src, float* __restrict__ dst,
                          int K, int N)
{
    __shared__ float t[32][33];
    const int n0 = blockIdx.x*32, k0 = blockIdx.y*32;
    const int tx = threadIdx.x & 31, tg = threadIdx.x >> 5;   // 256 threads
    #pragma unroll
    for (int i=0;i<4;i++) {
        int r = tg + i*8;
        t[r][tx] = src[(size_t)(k0+r)*N + n0 + tx];
    }
    __syncthreads();
    #pragma unroll
    for (int i=0;i<4;i++) {
        int r = tg + i*8;
        dst[(size_t)(n0+r)*K + k0 + tx] = tf32r(t[tx][r]);
    }
}

// =====================================================================
// TF32 GEMM via ldmatrix + mma.m16n8k8.
// 256x128x32 tiles, 8 warps (64x64 warp tiles).
// 3-stage cp.async pipeline, SINGLE __syncthreads per k-step.
// blockIdx.z selects (Bt, bias, D, alpha) -> fused QKV.
// =====================================================================
#define STAGE_FLOATS (384*36)                 // 13824
#define STAGE_BYTES  (STAGE_FLOATS*4)         // 55296
#define GEMM_SMEM_BYTES (3*STAGE_BYTES)       // 165888; epilogue 135168 fits

template<int OUTMODE,int EPI,int ROUND>
__launch_bounds__(256)
__global__ void tgemm_k(const float* __restrict__ A,
                        const float* __restrict__ B0, const float* __restrict__ B1, const float* __restrict__ B2,
                        const float* __restrict__ c0, const float* __restrict__ c1, const float* __restrict__ c2,
                        float* __restrict__ D0, float* __restrict__ D1, float* __restrict__ D2,
                        int M, int N, int K, float a0, float a1, float a2)
{
    extern __shared__ float sm[];
    const uint32_t smBase = (uint32_t)__cvta_generic_to_shared(sm);

    const int z = blockIdx.z;
    const float* Bt   = (z==0) ? B0 : (z==1) ? B1 : B2;
    const float* bias = (z==0) ? c0 : (z==1) ? c1 : c2;
    float*       C    = (z==0) ? D0 : (z==1) ? D1 : D2;
    const float alpha = (z==0) ? a0 : (z==1) ? a1 : a2;

    const int tileM = blockIdx.y * 256;
    const int tileN = blockIdx.x * 128;
    const int tid   = threadIdx.x;
    const int warpId= tid >> 5;
    const int lane  = tid & 31;
    const int wm    = warpId >> 1;
    const int wn    = warpId & 1;

    const int ldRow = tid >> 3;
    const int ldCol = (tid & 7) << 2;

    const float* aPtr[8];
    #pragma unroll
    for (int t=0;t<8;t++) {
        int gm = tileM + t*32 + ldRow;
        if (gm > M-1) gm = M-1;
        aPtr[t] = A + (size_t)gm*K + ldCol;
    }
    const float* bPtr[4];
    #pragma unroll
    for (int t=0;t<4;t++)
        bPtr[t] = Bt + (size_t)(tileN + t*32 + ldRow)*K + ldCol;

    const int aRowOff = (lane & 7) + ((lane >> 3) & 1) * 8;
    const int aKH     = (lane >> 4) * 4;
    const int bNOff   = (lane & 7) + (lane >> 4) * 8;
    const int bKH     = ((lane >> 3) & 1) * 4;

    const uint32_t aAddr0 = smBase + (uint32_t)(((wm*64 + aRowOff)*36 + aKH) * 4);
    const uint32_t bAddr0 = smBase + (uint32_t)((9216 + (wn*64 + bNOff)*36 + bKH) * 4);

    float acc[4][8][4];
    #pragma unroll
    for (int i=0;i<4;i++)
        #pragma unroll
        for (int j=0;j<8;j++)
            #pragma unroll
            for (int t=0;t<4;t++) acc[i][j][t] = 0.f;

    auto loadStage = [&](int k0, int st) {
        const uint32_t ab = smBase + (uint32_t)st*STAGE_BYTES;
        const uint32_t bb = ab + 9216u*4u;
        #pragma unroll
        for (int t=0;t<8;t++)
            cpa16(ab + (uint32_t)(((t*32 + ldRow)*36 + ldCol)*4), aPtr[t] + k0);
        #pragma unroll
        for (int t=0;t<4;t++)
            cpa16(bb + (uint32_t)(((t*32 + ldRow)*36 + ldCol)*4), bPtr[t] + k0);
        asm volatile("cp.async.commit_group;" ::: "memory");
    };

    const int NS = K >> 5;
    loadStage(0, 0);
    if (NS > 1) loadStage(32, 1);

    int st = 0;
    for (int s = 0; s < NS; s++) {
        if (s + 1 < NS) asm volatile("cp.async.wait_group 1;" ::: "memory");
        else            asm volatile("cp.async.wait_group 0;" ::: "memory");
        __syncthreads();

        if (s + 2 < NS) {
            int nst = st + 2; if (nst >= 3) nst -= 3;
            loadStage((s+2) << 5, nst);
        }

        const uint32_t aS = aAddr0 + (uint32_t)st*STAGE_BYTES;
        const uint32_t bS = bAddr0 + (uint32_t)st*STAGE_BYTES;
        #pragma unroll
        for (int ks=0; ks<4; ks++) {
            uint32_t a[4][4], b[4][4];
            #pragma unroll
            for (int mb=0; mb<4; mb++)
                ldsm4(aS + (uint32_t)(mb*16*36*4 + ks*32), a[mb][0], a[mb][1], a[mb][2], a[mb][3]);
            #pragma unroll
            for (int nb=0; nb<4; nb++)
                ldsm4(bS + (uint32_t)(nb*16*36*4 + ks*32), b[nb][0], b[nb][1], b[nb][2], b[nb][3]);
            #pragma unroll
            for (int mb=0; mb<4; mb++)
                #pragma unroll
                for (int j=0; j<8; j++)
                    mma_tf32(acc[mb][j], a[mb][0], a[mb][1], a[mb][2], a[mb][3],
                             b[j>>1][(j&1)*2], b[j>>1][(j&1)*2+1]);
        }
        if (++st == 3) st = 0;
    }
    __syncthreads();

    // ---- epilogue: stage 256x128 tile in smem (pitch 132), float4 writes ----
    {
        const int r0 = lane >> 2;
        const int cb = 2*(lane & 3);
        #pragma unroll
        for (int mb=0; mb<4; mb++) {
            #pragma unroll
            for (int j=0; j<8; j++) {
                int row = wm*64 + mb*16 + r0;
                int col = wn*64 + j*8 + cb;
                *reinterpret_cast<float2*>(&sm[row*132 + col])     = make_float2(acc[mb][j][0], acc[mb][j][1]);
                *reinterpret_cast<float2*>(&sm[(row+8)*132 + col]) = make_float2(acc[mb][j][2], acc[mb][j][3]);
            }
        }
    }
    __syncthreads();

    #pragma unroll
    for (int rr=0; rr<2; rr++) {
        const int row = rr*128 + (tid >> 1);
        const int gm  = tileM + row;
        if (gm >= M) continue;
        int b = 0, s = 0;
        if (OUTMODE == 1) { b = gm / SEQ; s = gm - b*SEQ; }
        #pragma unroll
        for (int f=0; f<16; f++) {
            int c  = (tid & 1)*64 + f*4;
            int gn = tileN + c;
            float4 v = *reinterpret_cast<const float4*>(&sm[row*132 + c]);
            v.x = (v.x + bias[gn  ]) * alpha;
            v.y = (v.y + bias[gn+1]) * alpha;
            v.z = (v.z + bias[gn+2]) * alpha;
            v.w = (v.w + bias[gn+3]) * alpha;
            if (EPI == 1) {
                v.x = gelu_exact(v.x); v.y = gelu_exact(v.y);
                v.z = gelu_exact(v.z); v.w = gelu_exact(v.w);
            }
            if (ROUND) {
                v.x = tf32r(v.x); v.y = tf32r(v.y); v.z = tf32r(v.z); v.w = tf32r(v.w);
            }
            if (OUTMODE == 0) {
                *reinterpret_cast<float4*>(&C[(size_t)gm*N + gn]) = v;
            } else {
                int h = gn >> 6, dd = gn & 63;
                size_t orow = (size_t)(b*NHEAD + h)*SEQ + s;
                *reinterpret_cast<float4*>(&C[orow*HDIM + dd]) = v;
            }
        }
    }
}

// =====================================================================
// Fused attention via ldmatrix + mma.m16n8k8 (R8 layout, sync trimmed)
// =====================================================================
#define OFF_K   0
#define OFF_V   (SEQP*VL)
#define OFF_QO  (OFF_V + 64*KL)
#define OFF_S   (OFF_QO + 64*VL)
#define ATTN_SMEM_FLOATS (OFF_S + 64*KL)
#define ATTN_SMEM_BYTES  (ATTN_SMEM_FLOATS*4)

__launch_bounds__(512)
__global__ void attn_k(const float* __restrict__ q, const float* __restrict__ k,
                       const float* __restrict__ v, float* __restrict__ ctx)
{
    extern __shared__ float sm[];
    const uint32_t smBase = (uint32_t)__cvta_generic_to_shared(sm);
    float* Ksm = sm + OFF_K;
    float* Vsm = sm + OFF_V;
    float* QO  = sm + OFF_QO;
    float* Ssm = sm + OFF_S;

    const int bh = blockIdx.x;
    const int b  = bh / NHEAD;
    const int h  = bh - b*NHEAD;
    const int tid    = threadIdx.x;
    const int warpId = tid >> 5;
    const int lane   = tid & 31;

    const float* qb = q + (size_t)bh*SEQ*HDIM;
    const float* kb = k + (size_t)bh*SEQ*HDIM;
    const float* vb = v + (size_t)bh*SEQ*HDIM;

    const int aRowOff = (lane & 7) + ((lane >> 3) & 1) * 8;
    const int aKH     = (lane >> 4) * 4;
    const int bNOff   = (lane & 7) + (lane >> 4) * 8;
    const int bKH     = ((lane >> 3) & 1) * 4;
    const int r0 = lane >> 2;
    const int cb = 2*(lane & 3);

    for (int idx = tid; idx < SEQP*16; idx += 512) {
        int t = idx >> 4, f = idx & 15;
        float4 val = (t < SEQ) ? *reinterpret_cast<const float4*>(&kb[(size_t)t*HDIM + f*4])
                               : make_float4(0.f,0.f,0.f,0.f);
        *reinterpret_cast<float4*>(&Ksm[t*VL + f*4]) = val;
    }
    for (int idx = tid; idx < SEQP*HDIM; idx += 512) {
        int t = idx >> 6, d = idx & 63;
        Vsm[d*KL + t] = (t < SEQ) ? vb[(size_t)t*HDIM + d] : 0.f;
    }
    __syncthreads();

    for (int s0 = 0; s0 < SEQ; s0 += 64) {
        for (int idx = tid; idx < 64*16; idx += 512) {
            int r = idx >> 4, f = idx & 15;
            int s = s0 + r;
            float4 val = (s < SEQ) ? *reinterpret_cast<const float4*>(&qb[(size_t)s*HDIM + f*4])
                                   : make_float4(0.f,0.f,0.f,0.f);
            *reinterpret_cast<float4*>(&QO[r*VL + f*4]) = val;
        }
        __syncthreads();

        for (int t = warpId; t < 52; t += 16) {
            int mi = t / 13, ni = t - (t/13)*13;
            float c0[4] = {0.f,0.f,0.f,0.f}, c1[4] = {0.f,0.f,0.f,0.f};
            const uint32_t aAddr = smBase + (uint32_t)((OFF_QO + (mi*16 + aRowOff)*VL + aKH)*4);
            const uint32_t bAddr = smBase + (uint32_t)((OFF_K  + (ni*16 + bNOff)*VL + bKH)*4);
            #pragma unroll
            for (int ks=0; ks<8; ks++) {
                uint32_t a0,a1,a2,a3, b0,b1,b2,b3;
                ldsm4(aAddr + ks*32, a0,a1,a2,a3);
                ldsm4(bAddr + ks*32, b0,b1,b2,b3);
                mma_tf32(c0, a0,a1,a2,a3, b0,b1);
                mma_tf32(c1, a0,a1,a2,a3, b2,b3);
            }
            {
                int row = mi*16 + r0, col = ni*16 + cb;
                *reinterpret_cast<float2*>(&Ssm[row*KL + col])         = make_float2(c0[0], c0[1]);
                *reinterpret_cast<float2*>(&Ssm[(row+8)*KL + col])     = make_float2(c0[2], c0[3]);
                *reinterpret_cast<float2*>(&Ssm[row*KL + col + 8])     = make_float2(c1[0], c1[1]);
                *reinterpret_cast<float2*>(&Ssm[(row+8)*KL + col + 8]) = make_float2(c1[2], c1[3]);
            }
        }
        __syncthreads();

        #pragma unroll
        for (int rr = 0; rr < 4; rr++) {
            int r = warpId*4 + rr;
            float* rowp = &Ssm[r*KL];
            float x[7];
            float m = -1e30f;
            #pragma unroll
            for (int i=0;i<7;i++) {
                int c = lane + i*32;
                x[i] = (c < SEQ) ? rowp[c] : -1e30f;
                m = fmaxf(m, x[i]);
            }
            #pragma unroll
            for (int o=16;o;o>>=1) m = fmaxf(m, __shfl_xor_sync(0xffffffffu, m, o));
            float sum = 0.f;
            #pragma unroll
            for (int i=0;i<7;i++) { x[i] = __expf(x[i] - m); sum += x[i]; }
            #pragma unroll
            for (int o=16;o;o>>=1) sum += __shfl_xor_sync(0xffffffffu, sum, o);
            float inv = 1.f / sum;
            #pragma unroll
            for (int i=0;i<7;i++) {
                int c = lane + i*32;
                if (c < SEQ)       rowp[c] = tf32r(x[i]*inv);
                else if (c < SEQP) rowp[c] = 0.f;
            }
        }
        __syncthreads();

        {
            int mi = warpId >> 2, ni = warpId & 3;
            float c0[4] = {0.f,0.f,0.f,0.f}, c1[4] = {0.f,0.f,0.f,0.f};
            const uint32_t aAddr = smBase + (uint32_t)((OFF_S + (mi*16 + aRowOff)*KL + aKH)*4);
            const uint32_t bAddr = smBase + (uint32_t)((OFF_V + (ni*16 + bNOff)*KL + bKH)*4);
            #pragma unroll
            for (int ks=0; ks<26; ks++) {
                uint32_t a0,a1,a2,a3, b0,b1,b2,b3;
                ldsm4(aAddr + ks*32, a0,a1,a2,a3);
                ldsm4(bAddr + ks*32, b0,b1,b2,b3);
                mma_tf32(c0, a0,a1,a2,a3, b0,b1);
                mma_tf32(c1, a0,a1,a2,a3, b2,b3);
            }
            {
                int row = mi*16 + r0, col = ni*16 + cb;
                *reinterpret_cast<float2*>(&QO[row*VL + col])         = make_float2(c0[0], c0[1]);
                *reinterpret_cast<float2*>(&QO[(row+8)*VL + col])     = make_float2(c0[2], c0[3]);
                *reinterpret_cast<float2*>(&QO[row*VL + col + 8])     = make_float2(c1[0], c1[1]);
                *reinterpret_cast<float2*>(&QO[(row+8)*VL + col + 8]) = make_float2(c1[2], c1[3]);
            }
        }
        __syncthreads();

        for (int idx = tid; idx < 64*16; idx += 512) {
            int r = idx >> 4, f = idx & 15;
            int s = s0 + r;
            if (s < SEQ) {
                float4 val = *reinterpret_cast<const float4*>(&QO[r*VL + f*4]);
                val.x=tf32r(val.x); val.y=tf32r(val.y); val.z=tf32r(val.z); val.w=tf32r(val.w);
                *reinterpret_cast<float4*>(&ctx[((size_t)(b*SEQ + s))*DIM + h*HDIM + f*4]) = val;
            }
        }
        __syncthreads();
    }
}

// ---------------- residual + LayerNorm (float4 vectorized) ----------------
// 192 threads/row, one float4 per thread.
__launch_bounds__(192)
__global__ void add_ln_k(const float* __restrict__ x, const float* __restrict__ y,
                         const float* __restrict__ g, const float* __restrict__ be,
                         float* __restrict__ out, float* __restrict__ outR)
{
    const int r = blockIdx.x;
    const int t = threadIdx.x;             // 0..191
    const float4 yv = *reinterpret_cast<const float4*>(&y[(size_t)r*DIM + t*4]);

    float s  = yv.x + yv.y + yv.z + yv.w;
    float sq = yv.x*yv.x + yv.y*yv.y + yv.z*yv.z + yv.w*yv.w;

    __shared__ float red[12];
    #pragma unroll
    for (int o=16;o;o>>=1) { s += __shfl_xor_sync(0xffffffffu, s, o); sq += __shfl_xor_sync(0xffffffffu, sq, o); }
    int w = t >> 5, lane = t & 31;
    if (lane == 0) { red[w] = s; red[w+6] = sq; }
    __syncthreads();
    if (t < 32) {
        s  = (lane < 6) ? red[lane]     : 0.f;
        sq = (lane < 6) ? red[lane + 6] : 0.f;
        #pragma unroll
        for (int o=4;o;o>>=1) { s += __shfl_xor_sync(0xffffffffu, s, o); sq += __shfl_xor_sync(0xffffffffu, sq, o); }
        if (lane == 0) { red[0] = s; red[1] = sq; }
    }
    __syncthreads();
    const float mu   = red[0] * (1.f/DIM);
    const float var  = red[1] * (1.f/DIM) - mu*mu;
    const float rstd = rsqrtf(var + LN_EPS);

    const float4 xv = *reinterpret_cast<const float4*>(&x[(size_t)r*DIM + t*4]);
    const float4 gv = *reinterpret_cast<const float4*>(&g[t*4]);
    const float4 bv = *reinterpret_cast<const float4*>(&be[t*4]);
    float4 o;
    o.x = xv.x + (yv.x - mu)*rstd*gv.x + bv.x;
    o.y = xv.y + (yv.y - mu)*rstd*gv.y + bv.y;
    o.z = xv.z + (yv.z - mu)*rstd*gv.z + bv.z;
    o.w = xv.w + (yv.w - mu)*rstd*gv.w + bv.w;
    *reinterpret_cast<float4*>(&out[(size_t)r*DIM + t*4]) = o;
    if (outR) {
        float4 orr;
        orr.x = tf32r(o.x); orr.y = tf32r(o.y); orr.z = tf32r(o.z); orr.w = tf32r(o.w);
        *reinterpret_cast<float4*>(&outR[(size_t)r*DIM + t*4]) = orr;
    }
}

// ---------------- launch ----------------
extern "C" void kernel_launch(void* const* d_in, const int* in_sizes, int n_in,
                              void* d_out, int out_size)
{
    const float* x   = (const float*)d_in[0];
    const float* Wq  = (const float*)d_in[1];
    const float* bq  = (const float*)d_in[2];
    const float* Wk  = (const float*)d_in[3];
    const float* bk  = (const float*)d_in[4];
    const float* Wv  = (const float*)d_in[5];
    const float* bv  = (const float*)d_in[6];
    const float* Wo  = (const float*)d_in[7];
    const float* bo  = (const float*)d_in[8];
    const float* W1  = (const float*)d_in[9];
    const float* b1  = (const float*)d_in[10];
    const float* W2  = (const float*)d_in[11];
    const float* b2  = (const float*)d_in[12];
    const float* g1  = (const float*)d_in[13];
    const float* be1 = (const float*)d_in[14];
    const float* g2  = (const float*)d_in[15];
    const float* be2 = (const float*)d_in[16];
    float* out = (float*)d_out;

    float *q,*k,*v,*ctx,*ao,*x1,*x1r,*xr,*hh,*mlp;
    float *wqT,*wkT,*wvT,*woT,*w1T,*w2T;
    cudaGetSymbolAddress((void**)&q,   g_q);
    cudaGetSymbolAddress((void**)&k,   g_k);
    cudaGetSymbolAddress((void**)&v,   g_v);
    cudaGetSymbolAddress((void**)&ctx, g_ctx);
    cudaGetSymbolAddress((void**)&ao,  g_ao);
    cudaGetSymbolAddress((void**)&x1,  g_x1);
    cudaGetSymbolAddress((void**)&x1r, g_x1r);
    cudaGetSymbolAddress((void**)&xr,  g_xr);
    cudaGetSymbolAddress((void**)&hh,  g_h);
    cudaGetSymbolAddress((void**)&mlp, g_mlp);
    cudaGetSymbolAddress((void**)&wqT, g_wqT);
    cudaGetSymbolAddress((void**)&wkT, g_wkT);
    cudaGetSymbolAddress((void**)&wvT, g_wvT);
    cudaGetSymbolAddress((void**)&woT, g_woT);
    cudaGetSymbolAddress((void**)&w1T, g_w1T);
    cudaGetSymbolAddress((void**)&w2T, g_w2T);

    cudaFuncSetAttribute(tgemm_k<1,0,1>, cudaFuncAttributeMaxDynamicSharedMemorySize, GEMM_SMEM_BYTES);
    cudaFuncSetAttribute(tgemm_k<0,0,0>, cudaFuncAttributeMaxDynamicSharedMemorySize, GEMM_SMEM_BYTES);
    cudaFuncSetAttribute(tgemm_k<0,1,1>, cudaFuncAttributeMaxDynamicSharedMemorySize, GEMM_SMEM_BYTES);
    cudaFuncSetAttribute(attn_k,         cudaFuncAttributeMaxDynamicSharedMemorySize, ATTN_SMEM_BYTES);

    // --- pre-pass: transpose+round weights, round x ---
    {
        dim3 tg(DIM/32, DIM/32);
        troundT_k<<<tg, 256>>>(Wq, wqT, DIM, DIM);
        troundT_k<<<tg, 256>>>(Wk, wkT, DIM, DIM);
        troundT_k<<<tg, 256>>>(Wv, wvT, DIM, DIM);
        troundT_k<<<tg, 256>>>(Wo, woT, DIM, DIM);
        dim3 tg1(HID/32, DIM/32);
        troundT_k<<<tg1, 256>>>(W1, w1T, DIM, HID);
        dim3 tg2(DIM/32, HID/32);
        troundT_k<<<tg2, 256>>>(W2, w2T, HID, DIM);
        int n = TOK*DIM/4;
        round_k<<<(n+255)/256, 256>>>(x, xr, n);
    }

    const int mtiles = (TOK + 255)/256;   // 50

    // --- fused QKV projection ---
    {
        dim3 grid(DIM/128, mtiles, 3);
        tgemm_k<1,0,1><<<grid, 256, GEMM_SMEM_BYTES>>>(xr, wqT, wkT, wvT, bq, bk, bv,
                                                       q, k, v, TOK, DIM, DIM,
                                                       0.125f, 1.0f, 1.0f);
    }

    // --- fused attention -> ctx (rounded) ---
    attn_k<<<BH, 512, ATTN_SMEM_BYTES>>>(q, k, v, ctx);

    // --- attn_out = ctx @ Wo + bo ---
    {
        dim3 grid(DIM/128, mtiles, 1);
        tgemm_k<0,0,0><<<grid, 256, GEMM_SMEM_BYTES>>>(ctx, woT, woT, woT, bo, bo, bo,
                                                       ao, ao, ao, TOK, DIM, DIM,
                                                       1.0f, 1.0f, 1.0f);
    }

    // --- x1 = x + LN(attn_out); rounded copy for MLP1 ---
    add_ln_k<<<TOK, 192>>>(x, ao, g1, be1, x1, x1r);

    // --- h = gelu(x1 @ W1 + b1) (rounded) ---
    {
        dim3 grid(HID/128, mtiles, 1);
        tgemm_k<0,1,1><<<grid, 256, GEMM_SMEM_BYTES>>>(x1r, w1T, w1T, w1T, b1, b1, b1,
                                                       hh, hh, hh, TOK, HID, DIM,
                                                       1.0f, 1.0f, 1.0f);
    }

    // --- mlp = h @ W2 + b2 ---
    {
        dim3 grid(DIM/128, mtiles, 1);
        tgemm_k<0,0,0><<<grid, 256, GEMM_SMEM_BYTES>>>(hh, w2T, w2T, w2T, b2, b2, b2,
                                                       mlp, mlp, mlp, TOK, DIM, HID,
                                                       1.0f, 1.0f, 1.0f);
    }

    // --- out = x1 + LN(mlp) ---
    add_ln_k<<<TOK, 192>>>(x1, mlp, g2, be2, out, nullptr);
}

// round 10
// speedup vs baseline: 1.9940x; 1.0392x over previous
#include <cuda_runtime.h>
#include <cuda_bf16.h>
#include <mma.h>
#include <math.h>
#include <stdint.h>

using namespace nvcuda;

// ---------------- problem constants ----------------
#define BATCH   64
#define SEQ     197
#define TOK     (BATCH*SEQ)      // 12608
#define DIM     768
#define NHEAD   12
#define HDIM    64
#define HID     3072
#define BH      (BATCH*NHEAD)    // 768
#define LN_EPS  1e-6f

// padded attention dims
#define SEQP    208
#define KL      212              // pitch for t-contiguous rows (S, V^T)
#define VL      68               // pitch for d-contiguous rows (Q, K)

// ---------------- scratch (device globals) ----------------
__device__ float g_q  [(long)BH*SEQ*HDIM];
__device__ float g_k  [(long)BH*SEQ*HDIM];
__device__ float g_v  [(long)BH*SEQ*HDIM];
__device__ float g_ctx[(long)TOK*DIM];
__device__ float g_ao [(long)TOK*DIM];
__device__ float g_x1 [(long)TOK*DIM];
__device__ float g_x1r[(long)TOK*DIM];
__device__ float g_xr [(long)TOK*DIM];
__device__ float g_h  [(long)TOK*HID];
__device__ float g_mlp[(long)TOK*DIM];
// transposed + tf32-rounded weights: [N][K]
__device__ float g_wqT[DIM*DIM];
__device__ float g_wkT[DIM*DIM];
__device__ float g_wvT[DIM*DIM];
__device__ float g_woT[DIM*DIM];
__device__ float g_w1T[(long)HID*DIM];
__device__ float g_w2T[(long)DIM*HID];

__device__ __forceinline__ float tf32r(float x) { return wmma::__float_to_tf32(x); }
__device__ __forceinline__ float gelu_exact(float v) {
    return 0.5f * v * (1.f + erff(v * 0.70710678118654752f));
}
__device__ __forceinline__ void cpa16(uint32_t dst, const float* src) {
    asm volatile("cp.async.cg.shared.global [%0], [%1], 16;" :: "r"(dst), "l"(src) : "memory");
}
__device__ __forceinline__ void ldsm4(uint32_t addr, uint32_t& r0, uint32_t& r1,
                                      uint32_t& r2, uint32_t& r3) {
    asm volatile("ldmatrix.sync.aligned.m8n8.x4.shared.b16 {%0,%1,%2,%3}, [%4];"
                 : "=r"(r0), "=r"(r1), "=r"(r2), "=r"(r3) : "r"(addr));
}
__device__ __forceinline__ void mma_tf32(float* c, uint32_t a0, uint32_t a1,
                                         uint32_t a2, uint32_t a3,
                                         uint32_t b0, uint32_t b1) {
    asm volatile("mma.sync.aligned.m16n8k8.row.col.f32.tf32.tf32.f32 "
                 "{%0,%1,%2,%3}, {%4,%5,%6,%7}, {%8,%9}, {%0,%1,%2,%3};"
                 : "+f"(c[0]), "+f"(c[1]), "+f"(c[2]), "+f"(c[3])
                 : "r"(a0), "r"(a1), "r"(a2), "r"(a3), "r"(b0), "r"(b1));
}

// ---------------- tf32 RN rounding kernel (float4) ----------------
__global__ void round_k(const float* __restrict__ src, float* __restrict__ dst, int n4)
{
    int i = blockIdx.x*blockDim.x + threadIdx.x;
    if (i < n4) {
        float4 v = reinterpret_cast<const float4*>(src)[i];
        v.x = tf32r(v.x); v.y = tf32r(v.y); v.z = tf32r(v.z); v.w = tf32r(v.w);
        reinterpret_cast<float4*>(dst)[i] = v;
    }
}

// ---------------- transpose + tf32-round: src[K][N] -> dst[N][K] ----------------
__global__ void troundT_k(const float* __restrict__ src, float* __restrict__ dst,
                          int K, int N)
{
    __shared__ float t[32][33];
    const int n0 = blockIdx.x*32, k0 = blockIdx.y*32;
    const int tx = threadIdx.x & 31, tg = threadIdx.x >> 5;
    #pragma unroll
    for (int i=0;i<4;i++) {
        int r = tg + i*8;
        t[r][tx] = src[(size_t)(k0+r)*N + n0 + tx];
    }
    __syncthreads();
    #pragma unroll
    for (int i=0;i<4;i++) {
        int r = tg + i*8;
        dst[(size_t)(n0+r)*K + k0 + tx] = tf32r(t[tx][r]);
    }
}

// =====================================================================
// TF32 GEMM via ldmatrix + mma.m16n8k8.
// 128x128x32 tiles, 8 warps (64x32 warp tiles), 2 CTAs/SM.
// 3-stage cp.async pipeline, single __syncthreads per k-step.
// blockIdx.z selects (Bt, bias, D, alpha) -> fused QKV.
// =====================================================================
#define STAGE_FLOATS (256*36)                 // A 128*36 + B 128*36 = 9216
#define STAGE_BYTES  (STAGE_FLOATS*4)         // 36864
#define GEMM_SMEM_BYTES (3*STAGE_BYTES)       // 110592; epilogue 128*132*4=67584 fits

template<int OUTMODE,int EPI,int ROUND>
__launch_bounds__(256, 2)
__global__ void tgemm_k(const float* __restrict__ A,
                        const float* __restrict__ B0, const float* __restrict__ B1, const float* __restrict__ B2,
                        const float* __restrict__ c0, const float* __restrict__ c1, const float* __restrict__ c2,
                        float* __restrict__ D0, float* __restrict__ D1, float* __restrict__ D2,
                        int M, int N, int K, float a0, float a1, float a2)
{
    extern __shared__ float sm[];
    const uint32_t smBase = (uint32_t)__cvta_generic_to_shared(sm);

    const int z = blockIdx.z;
    const float* Bt   = (z==0) ? B0 : (z==1) ? B1 : B2;
    const float* bias = (z==0) ? c0 : (z==1) ? c1 : c2;
    float*       C    = (z==0) ? D0 : (z==1) ? D1 : D2;
    const float alpha = (z==0) ? a0 : (z==1) ? a1 : a2;

    const int tileM = blockIdx.y * 128;
    const int tileN = blockIdx.x * 128;
    const int tid   = threadIdx.x;
    const int warpId= tid >> 5;
    const int lane  = tid & 31;
    const int wm    = warpId >> 2;      // 0..1  (64-row slabs)
    const int wn    = warpId & 3;       // 0..3  (32-col slabs)

    const int ldRow = tid >> 3;         // 0..31
    const int ldCol = (tid & 7) << 2;   // 0..28

    const float* aPtr[4];
    #pragma unroll
    for (int t=0;t<4;t++) {
        int gm = tileM + t*32 + ldRow;
        if (gm > M-1) gm = M-1;
        aPtr[t] = A + (size_t)gm*K + ldCol;
    }
    const float* bPtr[4];
    #pragma unroll
    for (int t=0;t<4;t++)
        bPtr[t] = Bt + (size_t)(tileN + t*32 + ldRow)*K + ldCol;

    const int aRowOff = (lane & 7) + ((lane >> 3) & 1) * 8;
    const int aKH     = (lane >> 4) * 4;
    const int bNOff   = (lane & 7) + (lane >> 4) * 8;
    const int bKH     = ((lane >> 3) & 1) * 4;

    const uint32_t aAddr0 = smBase + (uint32_t)(((wm*64 + aRowOff)*36 + aKH) * 4);
    const uint32_t bAddr0 = smBase + (uint32_t)((4608 + (wn*32 + bNOff)*36 + bKH) * 4);

    float acc[4][4][4];
    #pragma unroll
    for (int i=0;i<4;i++)
        #pragma unroll
        for (int j=0;j<4;j++)
            #pragma unroll
            for (int t=0;t<4;t++) acc[i][j][t] = 0.f;

    auto loadStage = [&](int k0, int st) {
        const uint32_t ab = smBase + (uint32_t)st*STAGE_BYTES;
        const uint32_t bb = ab + 4608u*4u;
        #pragma unroll
        for (int t=0;t<4;t++)
            cpa16(ab + (uint32_t)(((t*32 + ldRow)*36 + ldCol)*4), aPtr[t] + k0);
        #pragma unroll
        for (int t=0;t<4;t++)
            cpa16(bb + (uint32_t)(((t*32 + ldRow)*36 + ldCol)*4), bPtr[t] + k0);
        asm volatile("cp.async.commit_group;" ::: "memory");
    };

    const int NS = K >> 5;
    loadStage(0, 0);
    if (NS > 1) loadStage(32, 1);

    int st = 0;
    for (int s = 0; s < NS; s++) {
        if (s + 1 < NS) asm volatile("cp.async.wait_group 1;" ::: "memory");
        else            asm volatile("cp.async.wait_group 0;" ::: "memory");
        __syncthreads();

        if (s + 2 < NS) {
            int nst = st + 2; if (nst >= 3) nst -= 3;
            loadStage((s+2) << 5, nst);
        }

        const uint32_t aS = aAddr0 + (uint32_t)st*STAGE_BYTES;
        const uint32_t bS = bAddr0 + (uint32_t)st*STAGE_BYTES;
        #pragma unroll
        for (int ks=0; ks<4; ks++) {
            uint32_t a[4][4], b[2][4];
            #pragma unroll
            for (int mb=0; mb<4; mb++)
                ldsm4(aS + (uint32_t)(mb*16*36*4 + ks*32), a[mb][0], a[mb][1], a[mb][2], a[mb][3]);
            #pragma unroll
            for (int nb=0; nb<2; nb++)
                ldsm4(bS + (uint32_t)(nb*16*36*4 + ks*32), b[nb][0], b[nb][1], b[nb][2], b[nb][3]);
            #pragma unroll
            for (int mb=0; mb<4; mb++)
                #pragma unroll
                for (int j=0; j<4; j++)
                    mma_tf32(acc[mb][j], a[mb][0], a[mb][1], a[mb][2], a[mb][3],
                             b[j>>1][(j&1)*2], b[j>>1][(j&1)*2+1]);
        }
        if (++st == 3) st = 0;
    }
    __syncthreads();

    // ---- epilogue: stage 128x128 tile in smem (pitch 132), float4 writes ----
    {
        const int r0 = lane >> 2;
        const int cb = 2*(lane & 3);
        #pragma unroll
        for (int mb=0; mb<4; mb++) {
            #pragma unroll
            for (int j=0; j<4; j++) {
                int row = wm*64 + mb*16 + r0;
                int col = wn*32 + j*8 + cb;
                *reinterpret_cast<float2*>(&sm[row*132 + col])     = make_float2(acc[mb][j][0], acc[mb][j][1]);
                *reinterpret_cast<float2*>(&sm[(row+8)*132 + col]) = make_float2(acc[mb][j][2], acc[mb][j][3]);
            }
        }
    }
    __syncthreads();

    {
        const int row = tid >> 1;
        const int gm  = tileM + row;
        if (gm < M) {
            int b = 0, s = 0;
            if (OUTMODE == 1) { b = gm / SEQ; s = gm - b*SEQ; }
            #pragma unroll
            for (int f=0; f<16; f++) {
                int c  = (tid & 1)*64 + f*4;
                int gn = tileN + c;
                float4 v = *reinterpret_cast<const float4*>(&sm[row*132 + c]);
                v.x = (v.x + bias[gn  ]) * alpha;
                v.y = (v.y + bias[gn+1]) * alpha;
                v.z = (v.z + bias[gn+2]) * alpha;
                v.w = (v.w + bias[gn+3]) * alpha;
                if (EPI == 1) {
                    v.x = gelu_exact(v.x); v.y = gelu_exact(v.y);
                    v.z = gelu_exact(v.z); v.w = gelu_exact(v.w);
                }
                if (ROUND) {
                    v.x = tf32r(v.x); v.y = tf32r(v.y); v.z = tf32r(v.z); v.w = tf32r(v.w);
                }
                if (OUTMODE == 0) {
                    *reinterpret_cast<float4*>(&C[(size_t)gm*N + gn]) = v;
                } else {
                    int h = gn >> 6, dd = gn & 63;
                    size_t orow = (size_t)(b*NHEAD + h)*SEQ + s;
                    *reinterpret_cast<float4*>(&C[orow*HDIM + dd]) = v;
                }
            }
        }
    }
}

// =====================================================================
// Fused attention: one CTA per (bh, s-tile). 512 threads (16 warps).
// grid.x = BH*4; tail tile trims score/PV work via miMax.
// =====================================================================
#define OFF_K   0
#define OFF_V   (SEQP*VL)
#define OFF_QO  (OFF_V + 64*KL)
#define OFF_S   (OFF_QO + 64*VL)
#define ATTN_SMEM_FLOATS (OFF_S + 64*KL)
#define ATTN_SMEM_BYTES  (ATTN_SMEM_FLOATS*4)

__launch_bounds__(512)
__global__ void attn_k(const float* __restrict__ q, const float* __restrict__ k,
                       const float* __restrict__ v, float* __restrict__ ctx)
{
    extern __shared__ float sm[];
    const uint32_t smBase = (uint32_t)__cvta_generic_to_shared(sm);
    float* Ksm = sm + OFF_K;
    float* Vsm = sm + OFF_V;
    float* QO  = sm + OFF_QO;
    float* Ssm = sm + OFF_S;

    const int bh   = blockIdx.x >> 2;
    const int tile = blockIdx.x & 3;
    const int s0   = tile * 64;
    const int valid = (SEQ - s0) < 64 ? (SEQ - s0) : 64;   // 64,64,64,5
    const int miMax = (valid + 15) >> 4;

    const int b  = bh / NHEAD;
    const int h  = bh - b*NHEAD;
    const int tid    = threadIdx.x;
    const int warpId = tid >> 5;
    const int lane   = tid & 31;

    const float* qb = q + (size_t)bh*SEQ*HDIM;
    const float* kb = k + (size_t)bh*SEQ*HDIM;
    const float* vb = v + (size_t)bh*SEQ*HDIM;

    const int aRowOff = (lane & 7) + ((lane >> 3) & 1) * 8;
    const int aKH     = (lane >> 4) * 4;
    const int bNOff   = (lane & 7) + (lane >> 4) * 8;
    const int bKH     = ((lane >> 3) & 1) * 4;
    const int r0 = lane >> 2;
    const int cb = 2*(lane & 3);

    // ---- K direct [t][d], V transposed [d][t], Q tile ----
    for (int idx = tid; idx < SEQP*16; idx += 512) {
        int t = idx >> 4, f = idx & 15;
        float4 val = (t < SEQ) ? *reinterpret_cast<const float4*>(&kb[(size_t)t*HDIM + f*4])
                               : make_float4(0.f,0.f,0.f,0.f);
        *reinterpret_cast<float4*>(&Ksm[t*VL + f*4]) = val;
    }
    for (int idx = tid; idx < SEQP*HDIM; idx += 512) {
        int t = idx >> 6, d = idx & 63;
        Vsm[d*KL + t] = (t < SEQ) ? vb[(size_t)t*HDIM + d] : 0.f;
    }
    for (int idx = tid; idx < 64*16; idx += 512) {
        int r = idx >> 4, f = idx & 15;
        int s = s0 + r;
        float4 val = (s < SEQ) ? *reinterpret_cast<const float4*>(&qb[(size_t)s*HDIM + f*4])
                               : make_float4(0.f,0.f,0.f,0.f);
        *reinterpret_cast<float4*>(&QO[r*VL + f*4]) = val;
    }
    __syncthreads();

    // ---- scores: miMax x 13 warp tiles ----
    for (int t = warpId; t < miMax*13; t += 16) {
        int mi = t / 13, ni = t - (t/13)*13;
        float c0[4] = {0.f,0.f,0.f,0.f}, c1[4] = {0.f,0.f,0.f,0.f};
        const uint32_t aAddr = smBase + (uint32_t)((OFF_QO + (mi*16 + aRowOff)*VL + aKH)*4);
        const uint32_t bAddr = smBase + (uint32_t)((OFF_K  + (ni*16 + bNOff)*VL + bKH)*4);
        #pragma unroll
        for (int ks=0; ks<8; ks++) {
            uint32_t a0,a1,a2,a3, b0,b1,b2,b3;
            ldsm4(aAddr + ks*32, a0,a1,a2,a3);
            ldsm4(bAddr + ks*32, b0,b1,b2,b3);
            mma_tf32(c0, a0,a1,a2,a3, b0,b1);
            mma_tf32(c1, a0,a1,a2,a3, b2,b3);
        }
        {
            int row = mi*16 + r0, col = ni*16 + cb;
            *reinterpret_cast<float2*>(&Ssm[row*KL + col])         = make_float2(c0[0], c0[1]);
            *reinterpret_cast<float2*>(&Ssm[(row+8)*KL + col])     = make_float2(c0[2], c0[3]);
            *reinterpret_cast<float2*>(&Ssm[row*KL + col + 8])     = make_float2(c1[0], c1[1]);
            *reinterpret_cast<float2*>(&Ssm[(row+8)*KL + col + 8]) = make_float2(c1[2], c1[3]);
        }
    }
    __syncthreads();

    // ---- softmax: rows [0, miMax*16), one row per warp per pass ----
    for (int rr = 0; rr < miMax; rr++) {
        int r = rr*16 + warpId;
        if (r >= miMax*16) break;
        float* rowp = &Ssm[r*KL];
        float x[7];
        float m = -1e30f;
        #pragma unroll
        for (int i=0;i<7;i++) {
            int c = lane + i*32;
            x[i] = (c < SEQ) ? rowp[c] : -1e30f;
            m = fmaxf(m, x[i]);
        }
        #pragma unroll
        for (int o=16;o;o>>=1) m = fmaxf(m, __shfl_xor_sync(0xffffffffu, m, o));
        float sum = 0.f;
        #pragma unroll
        for (int i=0;i<7;i++) { x[i] = __expf(x[i] - m); sum += x[i]; }
        #pragma unroll
        for (int o=16;o;o>>=1) sum += __shfl_xor_sync(0xffffffffu, sum, o);
        float inv = 1.f / sum;
        #pragma unroll
        for (int i=0;i<7;i++) {
            int c = lane + i*32;
            if (c < SEQ)       rowp[c] = tf32r(x[i]*inv);
            else if (c < SEQP) rowp[c] = 0.f;
        }
    }
    __syncthreads();

    // ---- O = P @ V: miMax*4 warp tiles ----
    if (warpId < miMax*4) {
        int mi = warpId >> 2, ni = warpId & 3;
        float c0[4] = {0.f,0.f,0.f,0.f}, c1[4] = {0.f,0.f,0.f,0.f};
        const uint32_t aAddr = smBase + (uint32_t)((OFF_S + (mi*16 + aRowOff)*KL + aKH)*4);
        const uint32_t bAddr = smBase + (uint32_t)((OFF_V + (ni*16 + bNOff)*KL + bKH)*4);
        #pragma unroll
        for (int ks=0; ks<26; ks++) {
            uint32_t a0,a1,a2,a3, b0,b1,b2,b3;
            ldsm4(aAddr + ks*32, a0,a1,a2,a3);
            ldsm4(bAddr + ks*32, b0,b1,b2,b3);
            mma_tf32(c0, a0,a1,a2,a3, b0,b1);
            mma_tf32(c1, a0,a1,a2,a3, b2,b3);
        }
        {
            int row = mi*16 + r0, col = ni*16 + cb;
            *reinterpret_cast<float2*>(&QO[row*VL + col])         = make_float2(c0[0], c0[1]);
            *reinterpret_cast<float2*>(&QO[(row+8)*VL + col])     = make_float2(c0[2], c0[3]);
            *reinterpret_cast<float2*>(&QO[row*VL + col + 8])     = make_float2(c1[0], c1[1]);
            *reinterpret_cast<float2*>(&QO[(row+8)*VL + col + 8]) = make_float2(c1[2], c1[3]);
        }
    }
    __syncthreads();

    // ---- write ctx rows (rounded) ----
    for (int idx = tid; idx < valid*16; idx += 512) {
        int r = idx >> 4, f = idx & 15;
        int s = s0 + r;
        float4 val = *reinterpret_cast<const float4*>(&QO[r*VL + f*4]);
        val.x=tf32r(val.x); val.y=tf32r(val.y); val.z=tf32r(val.z); val.w=tf32r(val.w);
        *reinterpret_cast<float4*>(&ctx[((size_t)(b*SEQ + s))*DIM + h*HDIM + f*4]) = val;
    }
}

// ---------------- residual + LayerNorm (float4 vectorized) ----------------
__launch_bounds__(192)
__global__ void add_ln_k(const float* __restrict__ x, const float* __restrict__ y,
                         const float* __restrict__ g, const float* __restrict__ be,
                         float* __restrict__ out, float* __restrict__ outR)
{
    const int r = blockIdx.x;
    const int t = threadIdx.x;
    const float4 yv = *reinterpret_cast<const float4*>(&y[(size_t)r*DIM + t*4]);

    float s  = yv.x + yv.y + yv.z + yv.w;
    float sq = yv.x*yv.x + yv.y*yv.y + yv.z*yv.z + yv.w*yv.w;

    __shared__ float red[12];
    #pragma unroll
    for (int o=16;o;o>>=1) { s += __shfl_xor_sync(0xffffffffu, s, o); sq += __shfl_xor_sync(0xffffffffu, sq, o); }
    int w = t >> 5, lane = t & 31;
    if (lane == 0) { red[w] = s; red[w+6] = sq; }
    __syncthreads();
    if (t < 32) {
        s  = (lane < 6) ? red[lane]     : 0.f;
        sq = (lane < 6) ? red[lane + 6] : 0.f;
        #pragma unroll
        for (int o=4;o;o>>=1) { s += __shfl_xor_sync(0xffffffffu, s, o); sq += __shfl_xor_sync(0xffffffffu, sq, o); }
        if (lane == 0) { red[0] = s; red[1] = sq; }
    }
    __syncthreads();
    const float mu   = red[0] * (1.f/DIM);
    const float var  = red[1] * (1.f/DIM) - mu*mu;
    const float rstd = rsqrtf(var + LN_EPS);

    const float4 xv = *reinterpret_cast<const float4*>(&x[(size_t)r*DIM + t*4]);
    const float4 gv = *reinterpret_cast<const float4*>(&g[t*4]);
    const float4 bv = *reinterpret_cast<const float4*>(&be[t*4]);
    float4 o;
    o.x = xv.x + (yv.x - mu)*rstd*gv.x + bv.x;
    o.y = xv.y + (yv.y - mu)*rstd*gv.y + bv.y;
    o.z = xv.z + (yv.z - mu)*rstd*gv.z + bv.z;
    o.w = xv.w + (yv.w - mu)*rstd*gv.w + bv.w;
    *reinterpret_cast<float4*>(&out[(size_t)r*DIM + t*4]) = o;
    if (outR) {
        float4 orr;
        orr.x = tf32r(o.x); orr.y = tf32r(o.y); orr.z = tf32r(o.z); orr.w = tf32r(o.w);
        *reinterpret_cast<float4*>(&outR[(size_t)r*DIM + t*4]) = orr;
    }
}

// ---------------- launch ----------------
extern "C" void kernel_launch(void* const* d_in, const int* in_sizes, int n_in,
                              void* d_out, int out_size)
{
    const float* x   = (const float*)d_in[0];
    const float* Wq  = (const float*)d_in[1];
    const float* bq  = (const float*)d_in[2];
    const float* Wk  = (const float*)d_in[3];
    const float* bk  = (const float*)d_in[4];
    const float* Wv  = (const float*)d_in[5];
    const float* bv  = (const float*)d_in[6];
    const float* Wo  = (const float*)d_in[7];
    const float* bo  = (const float*)d_in[8];
    const float* W1  = (const float*)d_in[9];
    const float* b1  = (const float*)d_in[10];
    const float* W2  = (const float*)d_in[11];
    const float* b2  = (const float*)d_in[12];
    const float* g1  = (const float*)d_in[13];
    const float* be1 = (const float*)d_in[14];
    const float* g2  = (const float*)d_in[15];
    const float* be2 = (const float*)d_in[16];
    float* out = (float*)d_out;

    float *q,*k,*v,*ctx,*ao,*x1,*x1r,*xr,*hh,*mlp;
    float *wqT,*wkT,*wvT,*woT,*w1T,*w2T;
    cudaGetSymbolAddress((void**)&q,   g_q);
    cudaGetSymbolAddress((void**)&k,   g_k);
    cudaGetSymbolAddress((void**)&v,   g_v);
    cudaGetSymbolAddress((void**)&ctx, g_ctx);
    cudaGetSymbolAddress((void**)&ao,  g_ao);
    cudaGetSymbolAddress((void**)&x1,  g_x1);
    cudaGetSymbolAddress((void**)&x1r, g_x1r);
    cudaGetSymbolAddress((void**)&xr,  g_xr);
    cudaGetSymbolAddress((void**)&hh,  g_h);
    cudaGetSymbolAddress((void**)&mlp, g_mlp);
    cudaGetSymbolAddress((void**)&wqT, g_wqT);
    cudaGetSymbolAddress((void**)&wkT, g_wkT);
    cudaGetSymbolAddress((void**)&wvT, g_wvT);
    cudaGetSymbolAddress((void**)&woT, g_woT);
    cudaGetSymbolAddress((void**)&w1T, g_w1T);
    cudaGetSymbolAddress((void**)&w2T, g_w2T);

    cudaFuncSetAttribute(tgemm_k<1,0,1>, cudaFuncAttributeMaxDynamicSharedMemorySize, GEMM_SMEM_BYTES);
    cudaFuncSetAttribute(tgemm_k<0,0,0>, cudaFuncAttributeMaxDynamicSharedMemorySize, GEMM_SMEM_BYTES);
    cudaFuncSetAttribute(tgemm_k<0,1,1>, cudaFuncAttributeMaxDynamicSharedMemorySize, GEMM_SMEM_BYTES);
    cudaFuncSetAttribute(attn_k,         cudaFuncAttributeMaxDynamicSharedMemorySize, ATTN_SMEM_BYTES);

    // --- pre-pass: transpose+round weights, round x ---
    {
        dim3 tg(DIM/32, DIM/32);
        troundT_k<<<tg, 256>>>(Wq, wqT, DIM, DIM);
        troundT_k<<<tg, 256>>>(Wk, wkT, DIM, DIM);
        troundT_k<<<tg, 256>>>(Wv, wvT, DIM, DIM);
        troundT_k<<<tg, 256>>>(Wo, woT, DIM, DIM);
        dim3 tg1(HID/32, DIM/32);
        troundT_k<<<tg1, 256>>>(W1, w1T, DIM, HID);
        dim3 tg2(DIM/32, HID/32);
        troundT_k<<<tg2, 256>>>(W2, w2T, HID, DIM);
        int n = TOK*DIM/4;
        round_k<<<(n+255)/256, 256>>>(x, xr, n);
    }

    const int mtiles = (TOK + 127)/128;   // 99

    // --- fused QKV projection ---
    {
        dim3 grid(DIM/128, mtiles, 3);
        tgemm_k<1,0,1><<<grid, 256, GEMM_SMEM_BYTES>>>(xr, wqT, wkT, wvT, bq, bk, bv,
                                                       q, k, v, TOK, DIM, DIM,
                                                       0.125f, 1.0f, 1.0f);
    }

    // --- fused attention -> ctx (rounded) ---
    attn_k<<<BH*4, 512, ATTN_SMEM_BYTES>>>(q, k, v, ctx);

    // --- attn_out = ctx @ Wo + bo ---
    {
        dim3 grid(DIM/128, mtiles, 1);
        tgemm_k<0,0,0><<<grid, 256, GEMM_SMEM_BYTES>>>(ctx, woT, woT, woT, bo, bo, bo,
                                                       ao, ao, ao, TOK, DIM, DIM,
                                                       1.0f, 1.0f, 1.0f);
    }

    // --- x1 = x + LN(attn_out); rounded copy for MLP1 ---
    add_ln_k<<<TOK, 192>>>(x, ao, g1, be1, x1, x1r);

    // --- h = gelu(x1 @ W1 + b1) (rounded) ---
    {
        dim3 grid(HID/128, mtiles, 1);
        tgemm_k<0,1,1><<<grid, 256, GEMM_SMEM_BYTES>>>(x1r, w1T, w1T, w1T, b1, b1, b1,
                                                       hh, hh, hh, TOK, HID, DIM,
                                                       1.0f, 1.0f, 1.0f);
    }

    // --- mlp = h @ W2 + b2 ---
    {
        dim3 grid(DIM/128, mtiles, 1);
        tgemm_k<0,0,0><<<grid, 256, GEMM_SMEM_BYTES>>>(hh, w2T, w2T, w2T, b2, b2, b2,
                                                       mlp, mlp, mlp, TOK, DIM, HID,
                                                       1.0f, 1.0f, 1.0f);
    }

    // --- out = x1 + LN(mlp) ---
    add_ln_k<<<TOK, 192>>>(x1, mlp, g2, be2, out, nullptr);
}